// round 11
// baseline (speedup 1.0000x reference)
#include <cuda_runtime.h>
#include <cuda.h>
#include <cuda_bf16.h>
#include <math.h>
#include <stdint.h>

// Problem constants
#define Vv 50000
#define Ee 300
#define EPAD 320
#define Hh 512
#define Ll 6
#define Nn 8192
#define Kk 4
#define NCAT 2048   // [iou (1536) | f (512)] concatenated output columns

// ---------------------------------------------------------------------------
// Feature gate: tcgen05 exists only on arch-accelerated / family passes.
// ---------------------------------------------------------------------------
#if defined(__CUDA_ARCH__) && (defined(__CUDA_ARCH_FEAT_SM103_ALL) || \
    defined(__CUDA_ARCH_FEAT_SM100_ALL) || defined(__CUDA_ARCH_FEAT_SM110_ALL) || \
    (defined(__CUDA_ARCH_FAMILY_SPECIFIC__) && (__CUDA_ARCH_FAMILY_SPECIFIC__ >= 1000)))
#define USE_TCGEN05 1
#else
#define USE_TCGEN05 0
#endif

// ---------------------------------------------------------------------------
// Scratch
// ---------------------------------------------------------------------------
__device__ __nv_bfloat16 g_xhi[Ll * Nn * EPAD];   // all levels batched
__device__ __nv_bfloat16 g_xlo[Ll * Nn * EPAD];
__device__ __nv_bfloat16 g_hhi[Nn * Hh];
__device__ __nv_bfloat16 g_hlo[Nn * Hh];

__device__ __nv_bfloat16 g_WcatT_hi[NCAT * EPAD];
__device__ __nv_bfloat16 g_WcatT_lo[NCAT * EPAD];
__device__ __nv_bfloat16 g_UcatT_hi[NCAT * Hh];
__device__ __nv_bfloat16 g_UcatT_lo[NCAT * Hh];

__device__ float g_xw4[Nn * NCAT];   // per-level x @ [W_iou|W_f]
__device__ float g_hu4[Nn * NCAT];   // h @ [U_iou|U_f]
__device__ float g_cbuf[2 * Nn * Hh];

// ---------------------------------------------------------------------------
// Common PTX helpers
// ---------------------------------------------------------------------------
__device__ __forceinline__ uint32_t smem_u32(const void* p) {
    uint32_t a;
    asm("{ .reg .u64 t; cvta.to.shared.u64 t, %1; cvt.u32.u64 %0, t; }"
        : "=r"(a) : "l"(p));
    return a;
}

__device__ __forceinline__ void cp16(uint32_t dst, const void* src) {
    asm volatile("cp.async.cg.shared.global [%0], [%1], 16;"
                 :: "r"(dst), "l"(src));
}

#define CP_COMMIT()  asm volatile("cp.async.commit_group;" ::: "memory")
#define CP_WAIT0()   asm volatile("cp.async.wait_group 0;" ::: "memory")
#define CP_WAIT1()   asm volatile("cp.async.wait_group 1;" ::: "memory")
#define MBAR_INIT(a, cnt) \
    asm volatile("mbarrier.init.shared.b64 [%0], %1;" :: "r"(a), "r"(cnt) : "memory")
#define MBAR_EXPECT_TX(a, bytes) \
    asm volatile("mbarrier.arrive.expect_tx.shared.b64 _, [%0], %1;" \
                 :: "r"(a), "r"(bytes) : "memory")

// SW64 descriptor (layout 4, SBO=32, LBO=1) — matches TMA SWIZZLE_64B layout
#define DESC_BASE_SW64 ((4ull << 61) | (1ull << 46) | (32ull << 32) | (1ull << 16))
#define MAKE_DESC64(a) (DESC_BASE_SW64 | (((uint64_t)((a) >> 4)) & 0x3FFFull))
// idesc: fp32 accum, bf16 A/B, K-major, M=128, N=256
#define IDESC_N256 (0x10u | 0x80u | 0x400u | (32u << 17) | (8u << 24))

#if USE_TCGEN05
__device__ __forceinline__ uint32_t elect1() {
    uint32_t p;
    asm volatile("{ .reg .pred p; elect.sync _|p, 0xFFFFFFFF; selp.b32 %0,1,0,p; }"
                 : "=r"(p));
    return p;
}

__device__ __forceinline__ void mbar_wait(uint32_t mbar, uint32_t parity) {
    asm volatile(
        "{\n\t.reg .pred P;\n\t"
        "WL_%=:\n\t"
        "mbarrier.try_wait.parity.acquire.cta.shared::cta.b64 P, [%0], %1, 0x989680;\n\t"
        "@P bra.uni WD_%=;\n\t"
        "bra.uni WL_%=;\n\t"
        "WD_%=:\n\t}"
        :: "r"(mbar), "r"(parity) : "memory");
}

__device__ __forceinline__ void tma2d(uint32_t smem, const CUtensorMap* map,
                                      int x, int y, uint32_t mbar) {
    asm volatile(
        "cp.async.bulk.tensor.2d.shared::cta.global.tile.mbarrier::complete_tx::bytes "
        "[%0], [%1, {%2, %3}], [%4];"
        :: "r"(smem), "l"(map), "r"(x), "r"(y), "r"(mbar) : "memory");
}

#define TC_ALLOC(a, n) \
    asm volatile("tcgen05.alloc.cta_group::1.sync.aligned.shared::cta.b32 [%0], %1;" \
                 :: "r"(a), "r"(n) : "memory")
#define TC_DEALLOC(t, n) \
    asm volatile("tcgen05.dealloc.cta_group::1.sync.aligned.b32 %0, %1;" :: "r"(t), "r"(n))
#define TC_RELINQ() \
    asm volatile("tcgen05.relinquish_alloc_permit.cta_group::1.sync.aligned;")
#define TC_COMMIT(m) \
    asm volatile("tcgen05.commit.cta_group::1.mbarrier::arrive::one.shared::cluster.b64 [%0];" \
                 :: "r"(m) : "memory")
#define TC_FENCE_AFTER()  asm volatile("tcgen05.fence::after_thread_sync;" ::: "memory")
#define TC_FENCE_BEFORE() asm volatile("tcgen05.fence::before_thread_sync;" ::: "memory")
#define TC_WAIT_LD()      asm volatile("tcgen05.wait::ld.sync.aligned;" ::: "memory")

__device__ __forceinline__ void mma_bf16_ss(uint32_t d, uint64_t ad, uint64_t bd,
                                            uint32_t idesc, uint32_t en) {
    asm volatile(
        "{\n\t.reg .pred p;\n\t"
        "setp.ne.u32 p, %4, 0;\n\t"
        "tcgen05.mma.cta_group::1.kind::f16 [%0], %1, %2, %3, {%5,%5,%5,%5}, p;\n\t}"
        :: "r"(d), "l"(ad), "l"(bd), "r"(idesc), "r"(en), "r"(0u) : "memory");
}

__device__ __forceinline__ void ldtm32(uint32_t* r, uint32_t taddr) {
    asm volatile(
        "tcgen05.ld.sync.aligned.32x32b.x32.b32 "
        "{%0, %1, %2, %3, %4, %5, %6, %7, %8, %9, %10, %11, %12, %13, %14, %15, "
        "%16, %17, %18, %19, %20, %21, %22, %23, %24, %25, %26, %27, %28, %29, %30, %31}, [%32];"
        : "=r"(r[0]), "=r"(r[1]), "=r"(r[2]), "=r"(r[3]), "=r"(r[4]), "=r"(r[5]),
          "=r"(r[6]), "=r"(r[7]), "=r"(r[8]), "=r"(r[9]), "=r"(r[10]), "=r"(r[11]),
          "=r"(r[12]), "=r"(r[13]), "=r"(r[14]), "=r"(r[15]), "=r"(r[16]), "=r"(r[17]),
          "=r"(r[18]), "=r"(r[19]), "=r"(r[20]), "=r"(r[21]), "=r"(r[22]), "=r"(r[23]),
          "=r"(r[24]), "=r"(r[25]), "=r"(r[26]), "=r"(r[27]), "=r"(r[28]), "=r"(r[29]),
          "=r"(r[30]), "=r"(r[31])
        : "r"(taddr));
}
#endif  // USE_TCGEN05

// Baseline-ISA warp MMA — fallback body
__device__ __forceinline__ void hmma16816(float* d, const uint32_t* a, const uint32_t* b) {
    asm volatile(
        "mma.sync.aligned.m16n8k16.row.col.f32.bf16.bf16.f32 "
        "{%0,%1,%2,%3}, {%4,%5,%6,%7}, {%8,%9}, {%0,%1,%2,%3};"
        : "+f"(d[0]), "+f"(d[1]), "+f"(d[2]), "+f"(d[3])
        : "r"(a[0]), "r"(a[1]), "r"(a[2]), "r"(a[3]), "r"(b[0]), "r"(b[1]));
}

__device__ __forceinline__ void split_bf16(float v, __nv_bfloat16& hi, __nv_bfloat16& lo) {
    hi = __float2bfloat16(v);
    lo = __float2bfloat16(v - __bfloat162float(hi));
}

// ---------------------------------------------------------------------------
// Weight prep: concatenated transposed split weights.
// ---------------------------------------------------------------------------
__global__ void prep_wcat_kernel(const float* __restrict__ Wa,
                                 const float* __restrict__ Wb,
                                 __nv_bfloat16* __restrict__ Thi,
                                 __nv_bfloat16* __restrict__ Tlo,
                                 int Korig, int Kpad)
{
    int idx = blockIdx.x * blockDim.x + threadIdx.x;
    if (idx >= NCAT * Kpad) return;
    int n = idx / Kpad;
    int k = idx - n * Kpad;
    float v = 0.f;
    if (k < Korig)
        v = (n < 1536) ? Wa[(size_t)k * 1536 + n] : Wb[(size_t)k * 512 + (n - 1536)];
    __nv_bfloat16 hi, lo;
    split_bf16(v, hi, lo);
    Thi[idx] = hi;
    Tlo[idx] = lo;
}

// ---------------------------------------------------------------------------
// Embedding gather + split, ALL levels in one launch
// ---------------------------------------------------------------------------
__global__ void gather_x_all_kernel(const float* __restrict__ embed,
                                    const int* __restrict__ vix,     // [L*N]
                                    const float* __restrict__ tmask, // [L*N]
                                    __nv_bfloat16* __restrict__ xhi,
                                    __nv_bfloat16* __restrict__ xlo)
{
    int idx = blockIdx.x * blockDim.x + threadIdx.x;
    const int QE = EPAD / 2;  // 160
    if (idx >= Ll * Nn * QE) return;
    int n = idx / QE;
    int e = (idx - n * QE) * 2;
    float m = tmask[n];
    float v0 = 0.f, v1 = 0.f;
    if (e < Ee) {
        const float* er = embed + (size_t)vix[n] * Ee + e;
        v0 = er[0] * m;
        v1 = er[1] * m;
    }
    __nv_bfloat16 h0, l0, h1, l1;
    split_bf16(v0, h0, l0);
    split_bf16(v1, h1, l1);
    *(__nv_bfloat162*)(xhi + (size_t)n * EPAD + e) = __nv_bfloat162(h0, h1);
    *(__nv_bfloat162*)(xlo + (size_t)n * EPAD + e) = __nv_bfloat162(l0, l1);
}

// ---------------------------------------------------------------------------
// Dual-job split-bf16 GEMM. Job 0 (blockIdx.y < yh): C0 = A0 @ B0^T (hu4);
// Job 1 (blockIdx.y >= yh):                          C1 = A1 @ B1^T (xw4).
// Each job: 256(M) x 256(N) tile per CTA, two TMEM accumulator regions,
// K-chunks of 32 (SW64), 3-stage mbarrier pipeline, TMA bulk loads.
// A tensor-map y coordinate offset per job (arow) selects level slice.
// ---------------------------------------------------------------------------
#define STAGE_BYTES 65536   // Ahi 16K | Alo 16K | Bhi 16K | Blo 16K (256 rows x 64B)
#define NSTAGE 3
#define GEMM_SMEM   (NSTAGE * STAGE_BYTES + 1024)

__global__ void __launch_bounds__(256)
gemm_dual_kernel(const __grid_constant__ CUtensorMap tmA0hi,
                 const __grid_constant__ CUtensorMap tmA0lo,
                 const __grid_constant__ CUtensorMap tmB0hi,
                 const __grid_constant__ CUtensorMap tmB0lo,
                 const __grid_constant__ CUtensorMap tmA1hi,
                 const __grid_constant__ CUtensorMap tmA1lo,
                 const __grid_constant__ CUtensorMap tmB1hi,
                 const __grid_constant__ CUtensorMap tmB1lo,
                 const __nv_bfloat16* __restrict__ A0hi,
                 const __nv_bfloat16* __restrict__ A0lo,
                 const __nv_bfloat16* __restrict__ B0hi,
                 const __nv_bfloat16* __restrict__ B0lo,
                 const __nv_bfloat16* __restrict__ A1hi,
                 const __nv_bfloat16* __restrict__ A1lo,
                 const __nv_bfloat16* __restrict__ B1hi,
                 const __nv_bfloat16* __restrict__ B1lo,
                 float* __restrict__ C0, float* __restrict__ C1,
                 int yh, int arow0, int arow1,
                 int Ks0, int Ks1, int Ncol)
{
    const int by = blockIdx.y;
    const int job = (by < yh) ? 0 : 1;
    const int m0 = (job ? (by - yh) : by) * 256;   // local C rows
    const int n0 = blockIdx.x * 256;
    const int arow = job ? arow1 : arow0;          // A tensor row offset
    const int Ks = job ? Ks1 : Ks0;
    const int NC = Ks >> 5;
    float* Cj = job ? C1 : C0;

#if USE_TCGEN05
    extern __shared__ char smem_raw[];
    const uint32_t sb = smem_u32(smem_raw);
    // ctrl: [0] tmem ptr; full@16,24,32  empty@40,48,56  done@64
    const uint32_t ctrl = sb;
    const uint32_t tiles = (sb + 80 + 1023) & ~1023u;

    const int tid = threadIdx.x;
    const int wid = tid >> 5;
    const int lid = tid & 31;

    const CUtensorMap* mAhi = job ? &tmA1hi : &tmA0hi;
    const CUtensorMap* mAlo = job ? &tmA1lo : &tmA0lo;
    const CUtensorMap* mBhi = job ? &tmB1hi : &tmB0hi;
    const CUtensorMap* mBlo = job ? &tmB1lo : &tmB0lo;

    if (wid == 0) TC_ALLOC(ctrl, 512);
    if (tid == 0) {
        MBAR_INIT(ctrl + 16, 1);    // full[0]  (expect_tx arrive)
        MBAR_INIT(ctrl + 24, 1);    // full[1]
        MBAR_INIT(ctrl + 32, 1);    // full[2]
        MBAR_INIT(ctrl + 40, 1);    // empty[0]
        MBAR_INIT(ctrl + 48, 1);    // empty[1]
        MBAR_INIT(ctrl + 56, 1);    // empty[2]
        MBAR_INIT(ctrl + 64, 1);    // done
    }
    __syncthreads();
    uint32_t tmem;
    asm("ld.shared.b32 %0, [%1];" : "=r"(tmem) : "r"(ctrl));

    if (wid == 4) {
        // ------------------- producer (1 elected thread) -------------------
        if (elect1()) {
            int s = 0, it = 0;
            for (int c = 0; c < NC; c++) {
                const uint32_t ph = 1u ^ ((uint32_t)it & 1u);
                mbar_wait(ctrl + 40 + s * 8, ph);   // fresh-barrier pass on first visit
                const uint32_t fullb = ctrl + 16 + s * 8;
                MBAR_EXPECT_TX(fullb, STAGE_BYTES);
                const uint32_t tb = tiles + s * STAGE_BYTES;
                const int kx = c * 32;
                tma2d(tb,         mAhi, kx, arow + m0, fullb);
                tma2d(tb + 16384, mAlo, kx, arow + m0, fullb);
                tma2d(tb + 32768, mBhi, kx, n0, fullb);
                tma2d(tb + 49152, mBlo, kx, n0, fullb);
                if (++s == NSTAGE) { s = 0; it++; }
            }
        }
    } else if (wid == 0 && elect1()) {
        // ------------------- consumer (1 thread) -------------------
        int s = 0, it = 0;
        for (int c = 0; c < NC; c++) {
            const uint32_t ph = (uint32_t)it & 1u;
            mbar_wait(ctrl + 16 + s * 8, ph);
            const uint32_t tb = tiles + s * STAGE_BYTES;
#pragma unroll
            for (int mh = 0; mh < 2; mh++) {
                const uint32_t dtm = tmem + mh * 256;
                uint64_t dah = MAKE_DESC64(tb + mh * 8192);
                uint64_t dal = MAKE_DESC64(tb + 16384 + mh * 8192);
                uint64_t dbh = MAKE_DESC64(tb + 32768);
                uint64_t dbl = MAKE_DESC64(tb + 49152);
#pragma unroll
                for (int ks = 0; ks < 2; ks++)
                    mma_bf16_ss(dtm, dah + 2 * ks, dbh + 2 * ks, IDESC_N256,
                                (c == 0 && ks == 0) ? 0u : 1u);
#pragma unroll
                for (int ks = 0; ks < 2; ks++)
                    mma_bf16_ss(dtm, dah + 2 * ks, dbl + 2 * ks, IDESC_N256, 1u);
#pragma unroll
                for (int ks = 0; ks < 2; ks++)
                    mma_bf16_ss(dtm, dal + 2 * ks, dbh + 2 * ks, IDESC_N256, 1u);
            }
            TC_COMMIT((c == NC - 1) ? (ctrl + 64) : (ctrl + 40 + s * 8));
            if (++s == NSTAGE) { s = 0; it++; }
        }
    }

    // ------------------- epilogue (warps 0-3) -------------------
    if (wid < 4) {
        mbar_wait(ctrl + 64, 0);
        TC_FENCE_AFTER();
#pragma unroll
        for (int mh = 0; mh < 2; mh++) {
            float* crow = Cj + (size_t)(m0 + mh * 128 + wid * 32 + lid) * Ncol + n0;
#pragma unroll
            for (int b = 0; b < 8; b++) {
                uint32_t r[32];
                ldtm32(r, tmem + mh * 256 + b * 32);
                TC_WAIT_LD();
#pragma unroll
                for (int j = 0; j < 32; j += 4) {
                    float4 v;
                    v.x = __uint_as_float(r[j + 0]);
                    v.y = __uint_as_float(r[j + 1]);
                    v.z = __uint_as_float(r[j + 2]);
                    v.w = __uint_as_float(r[j + 3]);
                    *(float4*)(crow + b * 32 + j) = v;
                }
            }
        }
        TC_FENCE_BEFORE();
    }

    __syncthreads();
    if (wid == 0) {
        TC_RELINQ();
        TC_DEALLOC(tmem, 512);
    }

#else  // ------------------------- mma.sync fallback -------------------------
    extern __shared__ char smem_raw[];
    const int tid = threadIdx.x;
    const int wid = tid >> 5;
    const int lane = tid & 31;
    const int wm = wid >> 1;
    const int wn = wid & 1;
    const int r4 = lane >> 2;
    const int tig = lane & 3;
    const int NC2 = Ks >> 5;

    const __nv_bfloat16* Ahi = job ? A1hi : A0hi;
    const __nv_bfloat16* Alo = job ? A1lo : A0lo;
    const __nv_bfloat16* Bhi = job ? B1hi : B0hi;
    const __nv_bfloat16* Blo = job ? B1lo : B0lo;

    for (int mq = 0; mq < 2; mq++) {
        const int ml = m0 + mq * 128;           // local C rows
        const int mg = arow + ml;               // global A rows
        for (int half = 0; half < 2; half++) {
            const int nn0 = n0 + half * 128;

            float acc[2][8][4];
#pragma unroll
            for (int i = 0; i < 2; i++)
#pragma unroll
                for (int j = 0; j < 8; j++)
#pragma unroll
                    for (int v = 0; v < 4; v++) acc[i][j][v] = 0.f;

            auto ldtile = [&](int buf, int k0) {
                uint32_t tb = smem_u32(smem_raw) + buf * 40960;
#pragma unroll
                for (int q = tid; q < 512; q += 256) {
                    int row = q >> 2;
                    int c = q & 3;
                    uint32_t d = tb + row * 80 + c * 16;
                    size_t ao = (size_t)(mg + row) * Ks + k0 + c * 8;
                    size_t bo = (size_t)(nn0 + row) * Ks + k0 + c * 8;
                    cp16(d,         Ahi + ao);
                    cp16(d + 10240, Alo + ao);
                    cp16(d + 20480, Bhi + bo);
                    cp16(d + 30720, Blo + bo);
                }
                CP_COMMIT();
            };

            ldtile(0, 0);

            for (int c = 0; c < NC2; c++) {
                const int cur = c & 1;
                if (c + 1 < NC2) {
                    ldtile(cur ^ 1, (c + 1) * 32);
                    CP_WAIT1();
                } else {
                    CP_WAIT0();
                }
                __syncthreads();

                const char* tb = smem_raw + cur * 40960;
#pragma unroll
                for (int kk = 0; kk < 32; kk += 16) {
                    uint32_t ahi[2][4], alo[2][4], bhi[8][2], blo[8][2];
#pragma unroll
                    for (int mi = 0; mi < 2; mi++) {
                        int row = wm * 32 + mi * 16 + r4;
                        int cb = (kk + tig * 2) * 2;
                        ahi[mi][0] = *(const uint32_t*)(tb + row * 80 + cb);
                        ahi[mi][1] = *(const uint32_t*)(tb + (row + 8) * 80 + cb);
                        ahi[mi][2] = *(const uint32_t*)(tb + row * 80 + cb + 16);
                        ahi[mi][3] = *(const uint32_t*)(tb + (row + 8) * 80 + cb + 16);
                        alo[mi][0] = *(const uint32_t*)(tb + 10240 + row * 80 + cb);
                        alo[mi][1] = *(const uint32_t*)(tb + 10240 + (row + 8) * 80 + cb);
                        alo[mi][2] = *(const uint32_t*)(tb + 10240 + row * 80 + cb + 16);
                        alo[mi][3] = *(const uint32_t*)(tb + 10240 + (row + 8) * 80 + cb + 16);
                    }
#pragma unroll
                    for (int ni = 0; ni < 8; ni++) {
                        int nr = wn * 64 + ni * 8 + r4;
                        int cb = (kk + tig * 2) * 2;
                        bhi[ni][0] = *(const uint32_t*)(tb + 20480 + nr * 80 + cb);
                        bhi[ni][1] = *(const uint32_t*)(tb + 20480 + nr * 80 + cb + 16);
                        blo[ni][0] = *(const uint32_t*)(tb + 30720 + nr * 80 + cb);
                        blo[ni][1] = *(const uint32_t*)(tb + 30720 + nr * 80 + cb + 16);
                    }
#pragma unroll
                    for (int mi = 0; mi < 2; mi++)
#pragma unroll
                        for (int ni = 0; ni < 8; ni++) {
                            hmma16816(acc[mi][ni], ahi[mi], bhi[ni]);
                            hmma16816(acc[mi][ni], ahi[mi], blo[ni]);
                            hmma16816(acc[mi][ni], alo[mi], bhi[ni]);
                        }
                }
                __syncthreads();
            }

#pragma unroll
            for (int mi = 0; mi < 2; mi++)
#pragma unroll
                for (int ni = 0; ni < 8; ni++) {
                    int row = ml + wm * 32 + mi * 16 + r4;
                    int col = nn0 + wn * 64 + ni * 8 + tig * 2;
                    *(float2*)(Cj + (size_t)row * Ncol + col) =
                        make_float2(acc[mi][ni][0], acc[mi][ni][1]);
                    *(float2*)(Cj + (size_t)(row + 8) * Ncol + col) =
                        make_float2(acc[mi][ni][2], acc[mi][ni][3]);
                }
            __syncthreads();
        }
    }
#endif
}

// ---------------------------------------------------------------------------
// Node update (fused gates + output-side child gathers + h split)
// ---------------------------------------------------------------------------
__device__ __forceinline__ float sigmoidf_(float v) {
    return 1.f / (1.f + __expf(-v));
}

template <bool LEAF>
__global__ void node_update_kernel(const float* __restrict__ xw4,
                                   const float* __restrict__ hu4,
                                   const float* __restrict__ b_iou,
                                   const float* __restrict__ b_f,
                                   const int* __restrict__ cidx,
                                   const float* __restrict__ cmask,
                                   const float* __restrict__ c_prev,
                                   float* __restrict__ c_out,
                                   __nv_bfloat16* __restrict__ hhi,
                                   __nv_bfloat16* __restrict__ hlo,
                                   float* __restrict__ h_f32)   // may be null
{
    int idx = blockIdx.x * blockDim.x + threadIdx.x;   // over Nn * Hh/2
    if (idx >= Nn * (Hh / 2)) return;
    int n = idx >> 8;              // / 256
    int j = (idx & 255) * 2;

    const float* xw = xw4 + (size_t)n * NCAT;
    float2 gi = *(const float2*)(xw + j);
    float2 go = *(const float2*)(xw + 512 + j);
    float2 gu = *(const float2*)(xw + 1024 + j);
    {
        float2 b0 = *(const float2*)(b_iou + j);
        float2 b1 = *(const float2*)(b_iou + 512 + j);
        float2 b2 = *(const float2*)(b_iou + 1024 + j);
        gi.x += b0.x; gi.y += b0.y;
        go.x += b1.x; go.y += b1.y;
        gu.x += b2.x; gu.y += b2.y;
    }

    float fcx = 0.f, fcy = 0.f;
    if (!LEAF) {
        float2 bf = *(const float2*)(b_f + j);
        float2 xf = *(const float2*)(xw + 1536 + j);
        xf.x += bf.x; xf.y += bf.y;
#pragma unroll
        for (int k = 0; k < Kk; k++) {
            int ci = cidx[n * Kk + k];
            float m = cmask[n * Kk + k];
            const float* hr = hu4 + (size_t)ci * NCAT;
            float2 hi_ = *(const float2*)(hr + j);
            float2 ho_ = *(const float2*)(hr + 512 + j);
            float2 hu_ = *(const float2*)(hr + 1024 + j);
            float2 hf_ = *(const float2*)(hr + 1536 + j);
            gi.x += m * hi_.x; gi.y += m * hi_.y;
            go.x += m * ho_.x; go.y += m * ho_.y;
            gu.x += m * hu_.x; gu.y += m * hu_.y;
            float fx = sigmoidf_(xf.x + m * hf_.x);
            float fy = sigmoidf_(xf.y + m * hf_.y);
            float2 cpv = *(const float2*)(c_prev + (size_t)ci * Hh + j);
            fcx += fx * cpv.x * m;
            fcy += fy * cpv.y * m;
        }
    }

    float cx = sigmoidf_(gi.x) * tanhf(gu.x) + fcx;
    float cy = sigmoidf_(gi.y) * tanhf(gu.y) + fcy;
    *(float2*)(c_out + (size_t)n * Hh + j) = make_float2(cx, cy);

    float hx = sigmoidf_(go.x) * tanhf(cx);
    float hy = sigmoidf_(go.y) * tanhf(cy);

    __nv_bfloat16 h0, l0, h1, l1;
    split_bf16(hx, h0, l0);
    split_bf16(hy, h1, l1);
    *(__nv_bfloat162*)(hhi + (size_t)n * Hh + j) = __nv_bfloat162(h0, h1);
    *(__nv_bfloat162*)(hlo + (size_t)n * Hh + j) = __nv_bfloat162(l0, l1);
    if (h_f32)
        *(float2*)(h_f32 + (size_t)n * Hh + j) = make_float2(hx, hy);
}

// ---------------------------------------------------------------------------
// Host-side tensor map encoding (driver entry point; no -lcuda link needed)
// ---------------------------------------------------------------------------
typedef CUresult (*EncodeTiledFn)(
    CUtensorMap*, CUtensorMapDataType, cuuint32_t, void*,
    const cuuint64_t*, const cuuint64_t*, const cuuint32_t*, const cuuint32_t*,
    CUtensorMapInterleave, CUtensorMapSwizzle, CUtensorMapL2promotion,
    CUtensorMapFloatOOBfill);

static void encode_map(EncodeTiledFn fn, CUtensorMap* m, void* ptr,
                       uint64_t cols, uint64_t rows) {
    cuuint64_t dims[2]    = {cols, rows};
    cuuint64_t strides[1] = {cols * 2};       // bf16 row pitch in bytes
    cuuint32_t box[2]     = {32, 256};        // 64B x 256 rows
    cuuint32_t es[2]      = {1, 1};
    fn(m, CU_TENSOR_MAP_DATA_TYPE_BFLOAT16, 2, ptr, dims, strides, box, es,
       CU_TENSOR_MAP_INTERLEAVE_NONE, CU_TENSOR_MAP_SWIZZLE_64B,
       CU_TENSOR_MAP_L2_PROMOTION_L2_128B, CU_TENSOR_MAP_FLOAT_OOB_FILL_NONE);
}

// ---------------------------------------------------------------------------
// Launch
// ---------------------------------------------------------------------------
extern "C" void kernel_launch(void* const* d_in, const int* in_sizes, int n_in,
                              void* d_out, int out_size)
{
    const int*   vocab_ix   = (const int*)d_in[0];
    const int*   child_idx  = (const int*)d_in[1];
    const float* token_mask = (const float*)d_in[2];
    const float* child_mask = (const float*)d_in[3];
    const float* embed      = (const float*)d_in[4];
    const float* W_iou      = (const float*)d_in[5];   // [E, 3H]
    const float* U_iou      = (const float*)d_in[6];   // [H, 3H]
    const float* b_iou      = (const float*)d_in[7];
    const float* W_f        = (const float*)d_in[8];   // [E, H]
    const float* U_f        = (const float*)d_in[9];   // [H, H]
    const float* b_f        = (const float*)d_in[10];
    float* out = (float*)d_out;

    cudaFuncSetAttribute(gemm_dual_kernel,
                         cudaFuncAttributeMaxDynamicSharedMemorySize, GEMM_SMEM);

    __nv_bfloat16 *xhi, *xlo, *hhi, *hlo;
    __nv_bfloat16 *WcatThi, *WcatTlo, *UcatThi, *UcatTlo;
    float *xw4, *hu4, *cbuf;
    cudaGetSymbolAddress((void**)&xhi, g_xhi);
    cudaGetSymbolAddress((void**)&xlo, g_xlo);
    cudaGetSymbolAddress((void**)&hhi, g_hhi);
    cudaGetSymbolAddress((void**)&hlo, g_hlo);
    cudaGetSymbolAddress((void**)&WcatThi, g_WcatT_hi);
    cudaGetSymbolAddress((void**)&WcatTlo, g_WcatT_lo);
    cudaGetSymbolAddress((void**)&UcatThi, g_UcatT_hi);
    cudaGetSymbolAddress((void**)&UcatTlo, g_UcatT_lo);
    cudaGetSymbolAddress((void**)&xw4, g_xw4);
    cudaGetSymbolAddress((void**)&hu4, g_hu4);
    cudaGetSymbolAddress((void**)&cbuf, g_cbuf);

    // Tensor maps (device-global addresses are launch-invariant; re-encoded
    // every call -> deterministic, no static guards)
    EncodeTiledFn encode_fn = nullptr;
    {
        void* fp = nullptr;
        cudaDriverEntryPointQueryResult st;
        cudaGetDriverEntryPoint("cuTensorMapEncodeTiled", &fp,
                                cudaEnableDefault, &st);
        encode_fn = (EncodeTiledFn)fp;
    }
    static CUtensorMap tm_xhi, tm_xlo, tm_Whi, tm_Wlo, tm_hhi, tm_hlo, tm_Uhi, tm_Ulo;
    encode_map(encode_fn, &tm_xhi, xhi, EPAD, (uint64_t)Ll * Nn);
    encode_map(encode_fn, &tm_xlo, xlo, EPAD, (uint64_t)Ll * Nn);
    encode_map(encode_fn, &tm_Whi, WcatThi, EPAD, NCAT);
    encode_map(encode_fn, &tm_Wlo, WcatTlo, EPAD, NCAT);
    encode_map(encode_fn, &tm_hhi, hhi, Hh, Nn);
    encode_map(encode_fn, &tm_hlo, hlo, Hh, Nn);
    encode_map(encode_fn, &tm_Uhi, UcatThi, Hh, NCAT);
    encode_map(encode_fn, &tm_Ulo, UcatTlo, Hh, NCAT);

    float* cp[2] = { cbuf, cbuf + (size_t)Nn * Hh };

    const int T = 256;

    // Weight prep + all-level x gather
    prep_wcat_kernel<<<(NCAT * EPAD + T - 1) / T, T>>>(W_iou, W_f, WcatThi, WcatTlo, Ee, EPAD);
    prep_wcat_kernel<<<(NCAT * Hh + T - 1) / T, T>>>(U_iou, U_f, UcatThi, UcatTlo, Hh, Hh);
    gather_x_all_kernel<<<(Ll * Nn * (EPAD / 2) + T - 1) / T, T>>>(
        embed, vocab_ix, token_mask, xhi, xlo);

    const int nu_blocks = (Nn * (Hh / 2) + T - 1) / T;

    // Leaf level (l = 5): xw4 only, iou column tiles only (grid.x = 6)
    gemm_dual_kernel<<<dim3(6, 32), 256, GEMM_SMEM>>>(
        tm_hhi, tm_hlo, tm_Uhi, tm_Ulo,     // job0 unused (yh = 0)
        tm_xhi, tm_xlo, tm_Whi, tm_Wlo,
        hhi, hlo, UcatThi, UcatTlo, xhi, xlo, WcatThi, WcatTlo,
        hu4, xw4, /*yh=*/0, /*arow0=*/0, /*arow1=*/5 * Nn,
        /*Ks0=*/Hh, /*Ks1=*/EPAD, NCAT);

    int cur = 0;
    node_update_kernel<true><<<nu_blocks, T>>>(
        xw4, nullptr, b_iou, b_f,
        nullptr, nullptr, nullptr, cp[cur], hhi, hlo, nullptr);
    cur ^= 1;

    for (int l = 4; l >= 0; --l) {
        const int prev = cur ^ 1;

        // Combined launch: job0 = hu4 (h_prev @ Ucat), job1 = xw4 level l
        gemm_dual_kernel<<<dim3(8, 64), 256, GEMM_SMEM>>>(
            tm_hhi, tm_hlo, tm_Uhi, tm_Ulo,
            tm_xhi, tm_xlo, tm_Whi, tm_Wlo,
            hhi, hlo, UcatThi, UcatTlo, xhi, xlo, WcatThi, WcatTlo,
            hu4, xw4, /*yh=*/32, /*arow0=*/0, /*arow1=*/l * Nn,
            /*Ks0=*/Hh, /*Ks1=*/EPAD, NCAT);

        float* hf32 = (l == 0) ? out : nullptr;
        node_update_kernel<false><<<nu_blocks, T>>>(
            xw4, hu4, b_iou, b_f,
            child_idx + l * Nn * Kk, child_mask + l * Nn * Kk,
            cp[prev], cp[cur], hhi, hlo, hf32);
        cur ^= 1;
    }
}

// round 12
// speedup vs baseline: 1.0005x; 1.0005x over previous
#include <cuda_runtime.h>
#include <cuda.h>
#include <cuda_bf16.h>
#include <math.h>
#include <stdint.h>

// Problem constants
#define Vv 50000
#define Ee 300
#define EPAD 320
#define Hh 512
#define Ll 6
#define Nn 8192
#define Kk 4
#define NCAT 2048   // [iou (1536) | f (512)] concatenated output columns

// ---------------------------------------------------------------------------
// Feature gate: tcgen05 exists only on arch-accelerated / family passes.
// ---------------------------------------------------------------------------
#if defined(__CUDA_ARCH__) && (defined(__CUDA_ARCH_FEAT_SM103_ALL) || \
    defined(__CUDA_ARCH_FEAT_SM100_ALL) || defined(__CUDA_ARCH_FEAT_SM110_ALL) || \
    (defined(__CUDA_ARCH_FAMILY_SPECIFIC__) && (__CUDA_ARCH_FAMILY_SPECIFIC__ >= 1000)))
#define USE_TCGEN05 1
#else
#define USE_TCGEN05 0
#endif

// ---------------------------------------------------------------------------
// Scratch
// ---------------------------------------------------------------------------
__device__ __nv_bfloat16 g_xhi[Ll * Nn * EPAD];   // all levels batched
__device__ __nv_bfloat16 g_xlo[Ll * Nn * EPAD];
__device__ __nv_bfloat16 g_hhi[Nn * Hh];
__device__ __nv_bfloat16 g_hlo[Nn * Hh];
__device__ __nv_bfloat16 g_hthi[Nn * Hh];          // child-sum h_tilde
__device__ __nv_bfloat16 g_htlo[Nn * Hh];

__device__ __nv_bfloat16 g_WcatT_hi[NCAT * EPAD];
__device__ __nv_bfloat16 g_WcatT_lo[NCAT * EPAD];
__device__ __nv_bfloat16 g_UcatT_hi[NCAT * Hh];
__device__ __nv_bfloat16 g_UcatT_lo[NCAT * Hh];

__device__ float g_xw4all[(size_t)Ll * Nn * NCAT];  // all-level x @ [W_iou|W_f]
__device__ float g_hu4[Nn * NCAT];                  // [ht@U_iou | h@U_f]
__device__ float g_cbuf[2 * Nn * Hh];

// ---------------------------------------------------------------------------
// Common PTX helpers
// ---------------------------------------------------------------------------
__device__ __forceinline__ uint32_t smem_u32(const void* p) {
    uint32_t a;
    asm("{ .reg .u64 t; cvta.to.shared.u64 t, %1; cvt.u32.u64 %0, t; }"
        : "=r"(a) : "l"(p));
    return a;
}

__device__ __forceinline__ void cp16(uint32_t dst, const void* src) {
    asm volatile("cp.async.cg.shared.global [%0], [%1], 16;"
                 :: "r"(dst), "l"(src));
}

#define CP_COMMIT()  asm volatile("cp.async.commit_group;" ::: "memory")
#define CP_WAIT0()   asm volatile("cp.async.wait_group 0;" ::: "memory")
#define CP_WAIT1()   asm volatile("cp.async.wait_group 1;" ::: "memory")
#define MBAR_INIT(a, cnt) \
    asm volatile("mbarrier.init.shared.b64 [%0], %1;" :: "r"(a), "r"(cnt) : "memory")
#define MBAR_EXPECT_TX(a, bytes) \
    asm volatile("mbarrier.arrive.expect_tx.shared.b64 _, [%0], %1;" \
                 :: "r"(a), "r"(bytes) : "memory")

// SW64 descriptor (layout 4, SBO=32, LBO=1) — matches TMA SWIZZLE_64B layout
#define DESC_BASE_SW64 ((4ull << 61) | (1ull << 46) | (32ull << 32) | (1ull << 16))
#define MAKE_DESC64(a) (DESC_BASE_SW64 | (((uint64_t)((a) >> 4)) & 0x3FFFull))
// idesc: fp32 accum, bf16 A/B, K-major, M=128, N=256
#define IDESC_N256 (0x10u | 0x80u | 0x400u | (32u << 17) | (8u << 24))

#if USE_TCGEN05
__device__ __forceinline__ uint32_t elect1() {
    uint32_t p;
    asm volatile("{ .reg .pred p; elect.sync _|p, 0xFFFFFFFF; selp.b32 %0,1,0,p; }"
                 : "=r"(p));
    return p;
}

__device__ __forceinline__ void mbar_wait(uint32_t mbar, uint32_t parity) {
    asm volatile(
        "{\n\t.reg .pred P;\n\t"
        "WL_%=:\n\t"
        "mbarrier.try_wait.parity.acquire.cta.shared::cta.b64 P, [%0], %1, 0x989680;\n\t"
        "@P bra.uni WD_%=;\n\t"
        "bra.uni WL_%=;\n\t"
        "WD_%=:\n\t}"
        :: "r"(mbar), "r"(parity) : "memory");
}

__device__ __forceinline__ void tma2d(uint32_t smem, const CUtensorMap* map,
                                      int x, int y, uint32_t mbar) {
    asm volatile(
        "cp.async.bulk.tensor.2d.shared::cta.global.tile.mbarrier::complete_tx::bytes "
        "[%0], [%1, {%2, %3}], [%4];"
        :: "r"(smem), "l"(map), "r"(x), "r"(y), "r"(mbar) : "memory");
}

#define TC_ALLOC(a, n) \
    asm volatile("tcgen05.alloc.cta_group::1.sync.aligned.shared::cta.b32 [%0], %1;" \
                 :: "r"(a), "r"(n) : "memory")
#define TC_DEALLOC(t, n) \
    asm volatile("tcgen05.dealloc.cta_group::1.sync.aligned.b32 %0, %1;" :: "r"(t), "r"(n))
#define TC_RELINQ() \
    asm volatile("tcgen05.relinquish_alloc_permit.cta_group::1.sync.aligned;")
#define TC_COMMIT(m) \
    asm volatile("tcgen05.commit.cta_group::1.mbarrier::arrive::one.shared::cluster.b64 [%0];" \
                 :: "r"(m) : "memory")
#define TC_FENCE_AFTER()  asm volatile("tcgen05.fence::after_thread_sync;" ::: "memory")
#define TC_FENCE_BEFORE() asm volatile("tcgen05.fence::before_thread_sync;" ::: "memory")
#define TC_WAIT_LD()      asm volatile("tcgen05.wait::ld.sync.aligned;" ::: "memory")

__device__ __forceinline__ void mma_bf16_ss(uint32_t d, uint64_t ad, uint64_t bd,
                                            uint32_t idesc, uint32_t en) {
    asm volatile(
        "{\n\t.reg .pred p;\n\t"
        "setp.ne.u32 p, %4, 0;\n\t"
        "tcgen05.mma.cta_group::1.kind::f16 [%0], %1, %2, %3, {%5,%5,%5,%5}, p;\n\t}"
        :: "r"(d), "l"(ad), "l"(bd), "r"(idesc), "r"(en), "r"(0u) : "memory");
}

__device__ __forceinline__ void ldtm32(uint32_t* r, uint32_t taddr) {
    asm volatile(
        "tcgen05.ld.sync.aligned.32x32b.x32.b32 "
        "{%0, %1, %2, %3, %4, %5, %6, %7, %8, %9, %10, %11, %12, %13, %14, %15, "
        "%16, %17, %18, %19, %20, %21, %22, %23, %24, %25, %26, %27, %28, %29, %30, %31}, [%32];"
        : "=r"(r[0]), "=r"(r[1]), "=r"(r[2]), "=r"(r[3]), "=r"(r[4]), "=r"(r[5]),
          "=r"(r[6]), "=r"(r[7]), "=r"(r[8]), "=r"(r[9]), "=r"(r[10]), "=r"(r[11]),
          "=r"(r[12]), "=r"(r[13]), "=r"(r[14]), "=r"(r[15]), "=r"(r[16]), "=r"(r[17]),
          "=r"(r[18]), "=r"(r[19]), "=r"(r[20]), "=r"(r[21]), "=r"(r[22]), "=r"(r[23]),
          "=r"(r[24]), "=r"(r[25]), "=r"(r[26]), "=r"(r[27]), "=r"(r[28]), "=r"(r[29]),
          "=r"(r[30]), "=r"(r[31])
        : "r"(taddr));
}
#endif  // USE_TCGEN05

// Baseline-ISA warp MMA — fallback body
__device__ __forceinline__ void hmma16816(float* d, const uint32_t* a, const uint32_t* b) {
    asm volatile(
        "mma.sync.aligned.m16n8k16.row.col.f32.bf16.bf16.f32 "
        "{%0,%1,%2,%3}, {%4,%5,%6,%7}, {%8,%9}, {%0,%1,%2,%3};"
        : "+f"(d[0]), "+f"(d[1]), "+f"(d[2]), "+f"(d[3])
        : "r"(a[0]), "r"(a[1]), "r"(a[2]), "r"(a[3]), "r"(b[0]), "r"(b[1]));
}

__device__ __forceinline__ void split_bf16(float v, __nv_bfloat16& hi, __nv_bfloat16& lo) {
    hi = __float2bfloat16(v);
    lo = __float2bfloat16(v - __bfloat162float(hi));
}

// ---------------------------------------------------------------------------
// Weight prep: concatenated transposed split weights.
// ---------------------------------------------------------------------------
__global__ void prep_wcat_kernel(const float* __restrict__ Wa,
                                 const float* __restrict__ Wb,
                                 __nv_bfloat16* __restrict__ Thi,
                                 __nv_bfloat16* __restrict__ Tlo,
                                 int Korig, int Kpad)
{
    int idx = blockIdx.x * blockDim.x + threadIdx.x;
    if (idx >= NCAT * Kpad) return;
    int n = idx / Kpad;
    int k = idx - n * Kpad;
    float v = 0.f;
    if (k < Korig)
        v = (n < 1536) ? Wa[(size_t)k * 1536 + n] : Wb[(size_t)k * 512 + (n - 1536)];
    __nv_bfloat16 hi, lo;
    split_bf16(v, hi, lo);
    Thi[idx] = hi;
    Tlo[idx] = lo;
}

// ---------------------------------------------------------------------------
// Embedding gather + split, ALL levels in one launch
// ---------------------------------------------------------------------------
__global__ void gather_x_all_kernel(const float* __restrict__ embed,
                                    const int* __restrict__ vix,     // [L*N]
                                    const float* __restrict__ tmask, // [L*N]
                                    __nv_bfloat16* __restrict__ xhi,
                                    __nv_bfloat16* __restrict__ xlo)
{
    int idx = blockIdx.x * blockDim.x + threadIdx.x;
    const int QE = EPAD / 2;  // 160
    if (idx >= Ll * Nn * QE) return;
    int n = idx / QE;
    int e = (idx - n * QE) * 2;
    float m = tmask[n];
    float v0 = 0.f, v1 = 0.f;
    if (e < Ee) {
        const float* er = embed + (size_t)vix[n] * Ee + e;
        v0 = er[0] * m;
        v1 = er[1] * m;
    }
    __nv_bfloat16 h0, l0, h1, l1;
    split_bf16(v0, h0, l0);
    split_bf16(v1, h1, l1);
    *(__nv_bfloat162*)(xhi + (size_t)n * EPAD + e) = __nv_bfloat162(h0, h1);
    *(__nv_bfloat162*)(xlo + (size_t)n * EPAD + e) = __nv_bfloat162(l0, l1);
}

// ---------------------------------------------------------------------------
// Child-sum gather: ht[n,:] = sum_k cmask[n,k] * h[cidx[n,k],:]  (split hi/lo)
// ---------------------------------------------------------------------------
__global__ void gather_ht_kernel(const int* __restrict__ cidx,
                                 const float* __restrict__ cmask,
                                 const __nv_bfloat16* __restrict__ hhi,
                                 const __nv_bfloat16* __restrict__ hlo,
                                 __nv_bfloat16* __restrict__ hthi,
                                 __nv_bfloat16* __restrict__ htlo)
{
    int idx = blockIdx.x * blockDim.x + threadIdx.x;   // over Nn * Hh/2
    if (idx >= Nn * (Hh / 2)) return;
    int n = idx >> 8;
    int j = (idx & 255) * 2;
    float sx = 0.f, sy = 0.f;
#pragma unroll
    for (int k = 0; k < Kk; k++) {
        int ci = cidx[n * Kk + k];
        float m = cmask[n * Kk + k];
        __nv_bfloat162 h2 = *(const __nv_bfloat162*)(hhi + (size_t)ci * Hh + j);
        __nv_bfloat162 l2 = *(const __nv_bfloat162*)(hlo + (size_t)ci * Hh + j);
        sx += m * (__bfloat162float(h2.x) + __bfloat162float(l2.x));
        sy += m * (__bfloat162float(h2.y) + __bfloat162float(l2.y));
    }
    __nv_bfloat16 h0, l0, h1, l1;
    split_bf16(sx, h0, l0);
    split_bf16(sy, h1, l1);
    *(__nv_bfloat162*)(hthi + (size_t)n * Hh + j) = __nv_bfloat162(h0, h1);
    *(__nv_bfloat162*)(htlo + (size_t)n * Hh + j) = __nv_bfloat162(l0, l1);
}

// ---------------------------------------------------------------------------
// Split-bf16 GEMM with per-column-range A select (dual-A):
//   n0 <  nsplit : C[:, n0..] = A1 @ B[n0..]^T
//   n0 >= nsplit : C[:, n0..] = A2 @ B[n0..]^T
// Tile: 256x256 per CTA, two TMEM accumulators, K-chunks of 32 (SW64),
// 3-stage mbarrier pipeline, TMA bulk loads (R10 structure).
// ---------------------------------------------------------------------------
#define STAGE_BYTES 65536   // Ahi 16K | Alo 16K | Bhi 16K | Blo 16K (256 rows x 64B)
#define NSTAGE 3
#define GEMM_SMEM   (NSTAGE * STAGE_BYTES + 1024)

__global__ void __launch_bounds__(256)
gemm_split_kernel(const __grid_constant__ CUtensorMap tmA1hi,
                  const __grid_constant__ CUtensorMap tmA1lo,
                  const __grid_constant__ CUtensorMap tmA2hi,
                  const __grid_constant__ CUtensorMap tmA2lo,
                  const __grid_constant__ CUtensorMap tmBhi,
                  const __grid_constant__ CUtensorMap tmBlo,
                  const __nv_bfloat16* __restrict__ A1hi,
                  const __nv_bfloat16* __restrict__ A1lo,
                  const __nv_bfloat16* __restrict__ A2hi,
                  const __nv_bfloat16* __restrict__ A2lo,
                  const __nv_bfloat16* __restrict__ Bhi,
                  const __nv_bfloat16* __restrict__ Blo,
                  float* __restrict__ C,
                  int M, int Ks, int Ncol, int nsplit)
{
    const int m0 = blockIdx.y * 256;
    const int n0 = blockIdx.x * 256;
    const int NC = Ks >> 5;
    const bool jobB = (n0 >= nsplit);

#if USE_TCGEN05
    extern __shared__ char smem_raw[];
    const uint32_t sb = smem_u32(smem_raw);
    // ctrl: [0] tmem ptr; full@16,24,32  empty@40,48,56  done@64
    const uint32_t ctrl = sb;
    const uint32_t tiles = (sb + 80 + 1023) & ~1023u;

    const int tid = threadIdx.x;
    const int wid = tid >> 5;
    const int lid = tid & 31;

    // Leaf-level f-block tiles are never read (leaf node_update uses iou only)
    if (M == Ll * Nn && n0 >= 1536 && m0 >= 5 * Nn) return;

    const CUtensorMap* mAhi = jobB ? &tmA2hi : &tmA1hi;
    const CUtensorMap* mAlo = jobB ? &tmA2lo : &tmA1lo;

    if (wid == 0) TC_ALLOC(ctrl, 512);
    if (tid == 0) {
        MBAR_INIT(ctrl + 16, 1);    // full[0]  (expect_tx arrive)
        MBAR_INIT(ctrl + 24, 1);    // full[1]
        MBAR_INIT(ctrl + 32, 1);    // full[2]
        MBAR_INIT(ctrl + 40, 1);    // empty[0]
        MBAR_INIT(ctrl + 48, 1);    // empty[1]
        MBAR_INIT(ctrl + 56, 1);    // empty[2]
        MBAR_INIT(ctrl + 64, 1);    // done
    }
    __syncthreads();
    uint32_t tmem;
    asm("ld.shared.b32 %0, [%1];" : "=r"(tmem) : "r"(ctrl));

    if (wid == 4) {
        // ------------------- producer (1 elected thread) -------------------
        if (elect1()) {
            int s = 0, it = 0;
            for (int c = 0; c < NC; c++) {
                const uint32_t ph = 1u ^ ((uint32_t)it & 1u);
                mbar_wait(ctrl + 40 + s * 8, ph);   // fresh-barrier pass on first visit
                const uint32_t fullb = ctrl + 16 + s * 8;
                MBAR_EXPECT_TX(fullb, STAGE_BYTES);
                const uint32_t tb = tiles + s * STAGE_BYTES;
                const int kx = c * 32;
                tma2d(tb,         mAhi, kx, m0, fullb);
                tma2d(tb + 16384, mAlo, kx, m0, fullb);
                tma2d(tb + 32768, &tmBhi, kx, n0, fullb);
                tma2d(tb + 49152, &tmBlo, kx, n0, fullb);
                if (++s == NSTAGE) { s = 0; it++; }
            }
        }
    } else if (wid == 0 && elect1()) {
        // ------------------- consumer (1 thread) -------------------
        int s = 0, it = 0;
        for (int c = 0; c < NC; c++) {
            const uint32_t ph = (uint32_t)it & 1u;
            mbar_wait(ctrl + 16 + s * 8, ph);
            const uint32_t tb = tiles + s * STAGE_BYTES;
#pragma unroll
            for (int mh = 0; mh < 2; mh++) {
                const uint32_t dtm = tmem + mh * 256;
                uint64_t dah = MAKE_DESC64(tb + mh * 8192);
                uint64_t dal = MAKE_DESC64(tb + 16384 + mh * 8192);
                uint64_t dbh = MAKE_DESC64(tb + 32768);
                uint64_t dbl = MAKE_DESC64(tb + 49152);
#pragma unroll
                for (int ks = 0; ks < 2; ks++)
                    mma_bf16_ss(dtm, dah + 2 * ks, dbh + 2 * ks, IDESC_N256,
                                (c == 0 && ks == 0) ? 0u : 1u);
#pragma unroll
                for (int ks = 0; ks < 2; ks++)
                    mma_bf16_ss(dtm, dah + 2 * ks, dbl + 2 * ks, IDESC_N256, 1u);
#pragma unroll
                for (int ks = 0; ks < 2; ks++)
                    mma_bf16_ss(dtm, dal + 2 * ks, dbh + 2 * ks, IDESC_N256, 1u);
            }
            TC_COMMIT((c == NC - 1) ? (ctrl + 64) : (ctrl + 40 + s * 8));
            if (++s == NSTAGE) { s = 0; it++; }
        }
    }

    // ------------------- epilogue (warps 0-3) -------------------
    if (wid < 4) {
        mbar_wait(ctrl + 64, 0);
        TC_FENCE_AFTER();
#pragma unroll
        for (int mh = 0; mh < 2; mh++) {
            float* crow = C + (size_t)(m0 + mh * 128 + wid * 32 + lid) * Ncol + n0;
#pragma unroll
            for (int b = 0; b < 8; b++) {
                uint32_t r[32];
                ldtm32(r, tmem + mh * 256 + b * 32);
                TC_WAIT_LD();
#pragma unroll
                for (int j = 0; j < 32; j += 4) {
                    float4 v;
                    v.x = __uint_as_float(r[j + 0]);
                    v.y = __uint_as_float(r[j + 1]);
                    v.z = __uint_as_float(r[j + 2]);
                    v.w = __uint_as_float(r[j + 3]);
                    *(float4*)(crow + b * 32 + j) = v;
                }
            }
        }
        TC_FENCE_BEFORE();
    }

    __syncthreads();
    if (wid == 0) {
        TC_RELINQ();
        TC_DEALLOC(tmem, 512);
    }

#else  // ------------------------- mma.sync fallback -------------------------
    extern __shared__ char smem_raw[];
    const int tid = threadIdx.x;
    const int wid = tid >> 5;
    const int lane = tid & 31;
    const int wm = wid >> 1;
    const int wn = wid & 1;
    const int r4 = lane >> 2;
    const int tig = lane & 3;
    const int NC2 = Ks >> 5;

    if (M == Ll * Nn && n0 >= 1536 && m0 >= 5 * Nn) return;

    const __nv_bfloat16* Ahi = jobB ? A2hi : A1hi;
    const __nv_bfloat16* Alo = jobB ? A2lo : A1lo;

    for (int mq = 0; mq < 2; mq++) {
        const int ml = m0 + mq * 128;
        for (int half = 0; half < 2; half++) {
            const int nn0 = n0 + half * 128;

            float acc[2][8][4];
#pragma unroll
            for (int i = 0; i < 2; i++)
#pragma unroll
                for (int j = 0; j < 8; j++)
#pragma unroll
                    for (int v = 0; v < 4; v++) acc[i][j][v] = 0.f;

            auto ldtile = [&](int buf, int k0) {
                uint32_t tb = smem_u32(smem_raw) + buf * 40960;
#pragma unroll
                for (int q = tid; q < 512; q += 256) {
                    int row = q >> 2;
                    int c = q & 3;
                    uint32_t d = tb + row * 80 + c * 16;
                    size_t ao = (size_t)(ml + row) * Ks + k0 + c * 8;
                    size_t bo = (size_t)(nn0 + row) * Ks + k0 + c * 8;
                    cp16(d,         Ahi + ao);
                    cp16(d + 10240, Alo + ao);
                    cp16(d + 20480, Bhi + bo);
                    cp16(d + 30720, Blo + bo);
                }
                CP_COMMIT();
            };

            ldtile(0, 0);

            for (int c = 0; c < NC2; c++) {
                const int cur = c & 1;
                if (c + 1 < NC2) {
                    ldtile(cur ^ 1, (c + 1) * 32);
                    CP_WAIT1();
                } else {
                    CP_WAIT0();
                }
                __syncthreads();

                const char* tb = smem_raw + cur * 40960;
#pragma unroll
                for (int kk = 0; kk < 32; kk += 16) {
                    uint32_t ahi[2][4], alo[2][4], bhi[8][2], blo[8][2];
#pragma unroll
                    for (int mi = 0; mi < 2; mi++) {
                        int row = wm * 32 + mi * 16 + r4;
                        int cb = (kk + tig * 2) * 2;
                        ahi[mi][0] = *(const uint32_t*)(tb + row * 80 + cb);
                        ahi[mi][1] = *(const uint32_t*)(tb + (row + 8) * 80 + cb);
                        ahi[mi][2] = *(const uint32_t*)(tb + row * 80 + cb + 16);
                        ahi[mi][3] = *(const uint32_t*)(tb + (row + 8) * 80 + cb + 16);
                        alo[mi][0] = *(const uint32_t*)(tb + 10240 + row * 80 + cb);
                        alo[mi][1] = *(const uint32_t*)(tb + 10240 + (row + 8) * 80 + cb);
                        alo[mi][2] = *(const uint32_t*)(tb + 10240 + row * 80 + cb + 16);
                        alo[mi][3] = *(const uint32_t*)(tb + 10240 + (row + 8) * 80 + cb + 16);
                    }
#pragma unroll
                    for (int ni = 0; ni < 8; ni++) {
                        int nr = wn * 64 + ni * 8 + r4;
                        int cb = (kk + tig * 2) * 2;
                        bhi[ni][0] = *(const uint32_t*)(tb + 20480 + nr * 80 + cb);
                        bhi[ni][1] = *(const uint32_t*)(tb + 20480 + nr * 80 + cb + 16);
                        blo[ni][0] = *(const uint32_t*)(tb + 30720 + nr * 80 + cb);
                        blo[ni][1] = *(const uint32_t*)(tb + 30720 + nr * 80 + cb + 16);
                    }
#pragma unroll
                    for (int mi = 0; mi < 2; mi++)
#pragma unroll
                        for (int ni = 0; ni < 8; ni++) {
                            hmma16816(acc[mi][ni], ahi[mi], bhi[ni]);
                            hmma16816(acc[mi][ni], ahi[mi], blo[ni]);
                            hmma16816(acc[mi][ni], alo[mi], bhi[ni]);
                        }
                }
                __syncthreads();
            }

#pragma unroll
            for (int mi = 0; mi < 2; mi++)
#pragma unroll
                for (int ni = 0; ni < 8; ni++) {
                    int row = ml + wm * 32 + mi * 16 + r4;
                    int col = nn0 + wn * 64 + ni * 8 + tig * 2;
                    *(float2*)(C + (size_t)row * Ncol + col) =
                        make_float2(acc[mi][ni][0], acc[mi][ni][1]);
                    *(float2*)(C + (size_t)(row + 8) * Ncol + col) =
                        make_float2(acc[mi][ni][2], acc[mi][ni][3]);
                }
            __syncthreads();
        }
    }
#endif
}

// ---------------------------------------------------------------------------
// Node update. Non-leaf: iou pre-activations come from the node's OWN hu4 row
// (cols 0..1535 = ht@U_iou, already child-summed); only the narrow f-column
// (cols 1536..2047 = h@U_f) and c_prev are gathered per child.
// ---------------------------------------------------------------------------
__device__ __forceinline__ float sigmoidf_(float v) {
    return 1.f / (1.f + __expf(-v));
}

template <bool LEAF>
__global__ void node_update_kernel(const float* __restrict__ xw4,
                                   const float* __restrict__ hu4,
                                   const float* __restrict__ b_iou,
                                   const float* __restrict__ b_f,
                                   const int* __restrict__ cidx,
                                   const float* __restrict__ cmask,
                                   const float* __restrict__ c_prev,
                                   float* __restrict__ c_out,
                                   __nv_bfloat16* __restrict__ hhi,
                                   __nv_bfloat16* __restrict__ hlo,
                                   float* __restrict__ h_f32)   // may be null
{
    int idx = blockIdx.x * blockDim.x + threadIdx.x;   // over Nn * Hh/2
    if (idx >= Nn * (Hh / 2)) return;
    int n = idx >> 8;              // / 256
    int j = (idx & 255) * 2;

    const float* xw = xw4 + (size_t)n * NCAT;
    float2 gi = *(const float2*)(xw + j);
    float2 go = *(const float2*)(xw + 512 + j);
    float2 gu = *(const float2*)(xw + 1024 + j);
    {
        float2 b0 = *(const float2*)(b_iou + j);
        float2 b1 = *(const float2*)(b_iou + 512 + j);
        float2 b2 = *(const float2*)(b_iou + 1024 + j);
        gi.x += b0.x; gi.y += b0.y;
        go.x += b1.x; go.y += b1.y;
        gu.x += b2.x; gu.y += b2.y;
    }

    float fcx = 0.f, fcy = 0.f;
    if (!LEAF) {
        const float* hr = hu4 + (size_t)n * NCAT;   // own row: ht@U_iou
        float2 hi_ = *(const float2*)(hr + j);
        float2 ho_ = *(const float2*)(hr + 512 + j);
        float2 hu_ = *(const float2*)(hr + 1024 + j);
        gi.x += hi_.x; gi.y += hi_.y;
        go.x += ho_.x; go.y += ho_.y;
        gu.x += hu_.x; gu.y += hu_.y;

        float2 bf = *(const float2*)(b_f + j);
        float2 xf = *(const float2*)(xw + 1536 + j);
        xf.x += bf.x; xf.y += bf.y;
#pragma unroll
        for (int k = 0; k < Kk; k++) {
            int ci = cidx[n * Kk + k];
            float m = cmask[n * Kk + k];
            float2 hf_ = *(const float2*)(hu4 + (size_t)ci * NCAT + 1536 + j);
            float fx = sigmoidf_(xf.x + m * hf_.x);
            float fy = sigmoidf_(xf.y + m * hf_.y);
            float2 cpv = *(const float2*)(c_prev + (size_t)ci * Hh + j);
            fcx += fx * cpv.x * m;
            fcy += fy * cpv.y * m;
        }
    }

    float cx = sigmoidf_(gi.x) * tanhf(gu.x) + fcx;
    float cy = sigmoidf_(gi.y) * tanhf(gu.y) + fcy;
    *(float2*)(c_out + (size_t)n * Hh + j) = make_float2(cx, cy);

    float hx = sigmoidf_(go.x) * tanhf(cx);
    float hy = sigmoidf_(go.y) * tanhf(cy);

    __nv_bfloat16 h0, l0, h1, l1;
    split_bf16(hx, h0, l0);
    split_bf16(hy, h1, l1);
    *(__nv_bfloat162*)(hhi + (size_t)n * Hh + j) = __nv_bfloat162(h0, h1);
    *(__nv_bfloat162*)(hlo + (size_t)n * Hh + j) = __nv_bfloat162(l0, l1);
    if (h_f32)
        *(float2*)(h_f32 + (size_t)n * Hh + j) = make_float2(hx, hy);
}

// ---------------------------------------------------------------------------
// Host-side tensor map encoding (driver entry point; no -lcuda link needed)
// ---------------------------------------------------------------------------
typedef CUresult (*EncodeTiledFn)(
    CUtensorMap*, CUtensorMapDataType, cuuint32_t, void*,
    const cuuint64_t*, const cuuint64_t*, const cuuint32_t*, const cuuint32_t*,
    CUtensorMapInterleave, CUtensorMapSwizzle, CUtensorMapL2promotion,
    CUtensorMapFloatOOBfill);

static void encode_map(EncodeTiledFn fn, CUtensorMap* m, void* ptr,
                       uint64_t cols, uint64_t rows) {
    cuuint64_t dims[2]    = {cols, rows};
    cuuint64_t strides[1] = {cols * 2};       // bf16 row pitch in bytes
    cuuint32_t box[2]     = {32, 256};        // 64B x 256 rows
    cuuint32_t es[2]      = {1, 1};
    fn(m, CU_TENSOR_MAP_DATA_TYPE_BFLOAT16, 2, ptr, dims, strides, box, es,
       CU_TENSOR_MAP_INTERLEAVE_NONE, CU_TENSOR_MAP_SWIZZLE_64B,
       CU_TENSOR_MAP_L2_PROMOTION_L2_128B, CU_TENSOR_MAP_FLOAT_OOB_FILL_NONE);
}

// ---------------------------------------------------------------------------
// Launch
// ---------------------------------------------------------------------------
extern "C" void kernel_launch(void* const* d_in, const int* in_sizes, int n_in,
                              void* d_out, int out_size)
{
    const int*   vocab_ix   = (const int*)d_in[0];
    const int*   child_idx  = (const int*)d_in[1];
    const float* token_mask = (const float*)d_in[2];
    const float* child_mask = (const float*)d_in[3];
    const float* embed      = (const float*)d_in[4];
    const float* W_iou      = (const float*)d_in[5];   // [E, 3H]
    const float* U_iou      = (const float*)d_in[6];   // [H, 3H]
    const float* b_iou      = (const float*)d_in[7];
    const float* W_f        = (const float*)d_in[8];   // [E, H]
    const float* U_f        = (const float*)d_in[9];   // [H, H]
    const float* b_f        = (const float*)d_in[10];
    float* out = (float*)d_out;

    cudaFuncSetAttribute(gemm_split_kernel,
                         cudaFuncAttributeMaxDynamicSharedMemorySize, GEMM_SMEM);

    __nv_bfloat16 *xhi, *xlo, *hhi, *hlo, *hthi, *htlo;
    __nv_bfloat16 *WcatThi, *WcatTlo, *UcatThi, *UcatTlo;
    float *xw4all, *hu4, *cbuf;
    cudaGetSymbolAddress((void**)&xhi, g_xhi);
    cudaGetSymbolAddress((void**)&xlo, g_xlo);
    cudaGetSymbolAddress((void**)&hhi, g_hhi);
    cudaGetSymbolAddress((void**)&hlo, g_hlo);
    cudaGetSymbolAddress((void**)&hthi, g_hthi);
    cudaGetSymbolAddress((void**)&htlo, g_htlo);
    cudaGetSymbolAddress((void**)&WcatThi, g_WcatT_hi);
    cudaGetSymbolAddress((void**)&WcatTlo, g_WcatT_lo);
    cudaGetSymbolAddress((void**)&UcatThi, g_UcatT_hi);
    cudaGetSymbolAddress((void**)&UcatTlo, g_UcatT_lo);
    cudaGetSymbolAddress((void**)&xw4all, g_xw4all);
    cudaGetSymbolAddress((void**)&hu4, g_hu4);
    cudaGetSymbolAddress((void**)&cbuf, g_cbuf);

    // Tensor maps (device-global addresses launch-invariant; re-encoded every
    // call -> deterministic, no static guards)
    EncodeTiledFn encode_fn = nullptr;
    {
        void* fp = nullptr;
        cudaDriverEntryPointQueryResult st;
        cudaGetDriverEntryPoint("cuTensorMapEncodeTiled", &fp,
                                cudaEnableDefault, &st);
        encode_fn = (EncodeTiledFn)fp;
    }
    static CUtensorMap tm_xhi, tm_xlo, tm_Whi, tm_Wlo;
    static CUtensorMap tm_hhi, tm_hlo, tm_hthi, tm_htlo, tm_Uhi, tm_Ulo;
    encode_map(encode_fn, &tm_xhi, xhi, EPAD, (uint64_t)Ll * Nn);
    encode_map(encode_fn, &tm_xlo, xlo, EPAD, (uint64_t)Ll * Nn);
    encode_map(encode_fn, &tm_Whi, WcatThi, EPAD, NCAT);
    encode_map(encode_fn, &tm_Wlo, WcatTlo, EPAD, NCAT);
    encode_map(encode_fn, &tm_hhi, hhi, Hh, Nn);
    encode_map(encode_fn, &tm_hlo, hlo, Hh, Nn);
    encode_map(encode_fn, &tm_hthi, hthi, Hh, Nn);
    encode_map(encode_fn, &tm_htlo, htlo, Hh, Nn);
    encode_map(encode_fn, &tm_Uhi, UcatThi, Hh, NCAT);
    encode_map(encode_fn, &tm_Ulo, UcatTlo, Hh, NCAT);

    float* cp[2] = { cbuf, cbuf + (size_t)Nn * Hh };

    const int T = 256;

    // Weight prep + all-level x gather + batched xw4all GEMM (R10 schedule)
    prep_wcat_kernel<<<(NCAT * EPAD + T - 1) / T, T>>>(W_iou, W_f, WcatThi, WcatTlo, Ee, EPAD);
    prep_wcat_kernel<<<(NCAT * Hh + T - 1) / T, T>>>(U_iou, U_f, UcatThi, UcatTlo, Hh, Hh);
    gather_x_all_kernel<<<(Ll * Nn * (EPAD / 2) + T - 1) / T, T>>>(
        embed, vocab_ix, token_mask, xhi, xlo);

    // xw4all = x(all levels) @ [W_iou | W_f]   (A2 unused: nsplit = huge)
    gemm_split_kernel<<<dim3(NCAT / 256, Ll * Nn / 256), 256, GEMM_SMEM>>>(
        tm_xhi, tm_xlo, tm_xhi, tm_xlo, tm_Whi, tm_Wlo,
        xhi, xlo, xhi, xlo, WcatThi, WcatTlo,
        xw4all, Ll * Nn, EPAD, NCAT, 1 << 30);

    const int nu_blocks = (Nn * (Hh / 2) + T - 1) / T;

    int cur = 0;
    // Leaf level (l = 5)
    node_update_kernel<true><<<nu_blocks, T>>>(
        xw4all + (size_t)5 * Nn * NCAT, nullptr, b_iou, b_f,
        nullptr, nullptr, nullptr, cp[cur], hhi, hlo, nullptr);
    cur ^= 1;

    for (int l = 4; l >= 0; --l) {
        const int prev = cur ^ 1;

        // ht = child-sum of h  (cheap gather; h is L2-resident)
        gather_ht_kernel<<<nu_blocks, T>>>(
            child_idx + l * Nn * Kk, child_mask + l * Nn * Kk,
            hhi, hlo, hthi, htlo);

        // hu4 = [ht @ U_iou | h @ U_f]  (dual-A by column range, one launch)
        gemm_split_kernel<<<dim3(NCAT / 256, Nn / 256), 256, GEMM_SMEM>>>(
            tm_hthi, tm_htlo, tm_hhi, tm_hlo, tm_Uhi, tm_Ulo,
            hthi, htlo, hhi, hlo, UcatThi, UcatTlo,
            hu4, Nn, Hh, NCAT, 1536);

        float* hf32 = (l == 0) ? out : nullptr;
        node_update_kernel<false><<<nu_blocks, T>>>(
            xw4all + (size_t)l * Nn * NCAT, hu4, b_iou, b_f,
            child_idx + l * Nn * Kk, child_mask + l * Nn * Kk,
            cp[prev], cp[cur], hhi, hlo, hf32);
        cur ^= 1;
    }
}

// round 13
// speedup vs baseline: 1.0082x; 1.0077x over previous
#include <cuda_runtime.h>
#include <cuda.h>
#include <cuda_bf16.h>
#include <math.h>
#include <stdint.h>

// Problem constants
#define Vv 50000
#define Ee 300
#define EPAD 320
#define Hh 512
#define Ll 6
#define Nn 8192
#define Kk 4
#define NCAT 2048   // [iou (1536) | f (512)] concatenated output columns

// ---------------------------------------------------------------------------
// Feature gate: tcgen05 exists only on arch-accelerated / family passes.
// ---------------------------------------------------------------------------
#if defined(__CUDA_ARCH__) && (defined(__CUDA_ARCH_FEAT_SM103_ALL) || \
    defined(__CUDA_ARCH_FEAT_SM100_ALL) || defined(__CUDA_ARCH_FEAT_SM110_ALL) || \
    (defined(__CUDA_ARCH_FAMILY_SPECIFIC__) && (__CUDA_ARCH_FAMILY_SPECIFIC__ >= 1000)))
#define USE_TCGEN05 1
#else
#define USE_TCGEN05 0
#endif

// ---------------------------------------------------------------------------
// Scratch
// ---------------------------------------------------------------------------
__device__ __nv_bfloat16 g_xhi[Ll * Nn * EPAD];   // all levels batched
__device__ __nv_bfloat16 g_xlo[Ll * Nn * EPAD];
__device__ __nv_bfloat16 g_hhi[Nn * Hh];
__device__ __nv_bfloat16 g_hlo[Nn * Hh];

__device__ __nv_bfloat16 g_WcatT_hi[NCAT * EPAD];
__device__ __nv_bfloat16 g_WcatT_lo[NCAT * EPAD];
__device__ __nv_bfloat16 g_UcatT_hi[NCAT * Hh];
__device__ __nv_bfloat16 g_UcatT_lo[NCAT * Hh];

__device__ float g_xw4all[(size_t)Ll * Nn * NCAT];  // all-level x @ [W_iou|W_f]
__device__ float g_hu4[Nn * NCAT];                  // h @ [U_iou|U_f]
__device__ float g_cbuf[2 * Nn * Hh];

// ---------------------------------------------------------------------------
// Common PTX helpers
// ---------------------------------------------------------------------------
__device__ __forceinline__ uint32_t smem_u32(const void* p) {
    uint32_t a;
    asm("{ .reg .u64 t; cvta.to.shared.u64 t, %1; cvt.u32.u64 %0, t; }"
        : "=r"(a) : "l"(p));
    return a;
}

__device__ __forceinline__ void cp16(uint32_t dst, const void* src) {
    asm volatile("cp.async.cg.shared.global [%0], [%1], 16;"
                 :: "r"(dst), "l"(src));
}

#define CP_COMMIT()  asm volatile("cp.async.commit_group;" ::: "memory")
#define CP_WAIT0()   asm volatile("cp.async.wait_group 0;" ::: "memory")
#define CP_WAIT1()   asm volatile("cp.async.wait_group 1;" ::: "memory")
#define MBAR_INIT(a, cnt) \
    asm volatile("mbarrier.init.shared.b64 [%0], %1;" :: "r"(a), "r"(cnt) : "memory")
#define MBAR_EXPECT_TX(a, bytes) \
    asm volatile("mbarrier.arrive.expect_tx.shared.b64 _, [%0], %1;" \
                 :: "r"(a), "r"(bytes) : "memory")

// SW64 descriptor (layout 4, SBO=32, LBO=1) — matches TMA SWIZZLE_64B layout
#define DESC_BASE_SW64 ((4ull << 61) | (1ull << 46) | (32ull << 32) | (1ull << 16))
#define MAKE_DESC64(a) (DESC_BASE_SW64 | (((uint64_t)((a) >> 4)) & 0x3FFFull))
// idesc: fp32 accum, bf16 A/B, K-major, M=128, N=256
#define IDESC_N256 (0x10u | 0x80u | 0x400u | (32u << 17) | (8u << 24))

#if USE_TCGEN05
__device__ __forceinline__ uint32_t elect1() {
    uint32_t p;
    asm volatile("{ .reg .pred p; elect.sync _|p, 0xFFFFFFFF; selp.b32 %0,1,0,p; }"
                 : "=r"(p));
    return p;
}

__device__ __forceinline__ void mbar_wait(uint32_t mbar, uint32_t parity) {
    asm volatile(
        "{\n\t.reg .pred P;\n\t"
        "WL_%=:\n\t"
        "mbarrier.try_wait.parity.acquire.cta.shared::cta.b64 P, [%0], %1, 0x989680;\n\t"
        "@P bra.uni WD_%=;\n\t"
        "bra.uni WL_%=;\n\t"
        "WD_%=:\n\t}"
        :: "r"(mbar), "r"(parity) : "memory");
}

__device__ __forceinline__ void tma2d(uint32_t smem, const CUtensorMap* map,
                                      int x, int y, uint32_t mbar) {
    asm volatile(
        "cp.async.bulk.tensor.2d.shared::cta.global.tile.mbarrier::complete_tx::bytes "
        "[%0], [%1, {%2, %3}], [%4];"
        :: "r"(smem), "l"(map), "r"(x), "r"(y), "r"(mbar) : "memory");
}

#define TC_ALLOC(a, n) \
    asm volatile("tcgen05.alloc.cta_group::1.sync.aligned.shared::cta.b32 [%0], %1;" \
                 :: "r"(a), "r"(n) : "memory")
#define TC_DEALLOC(t, n) \
    asm volatile("tcgen05.dealloc.cta_group::1.sync.aligned.b32 %0, %1;" :: "r"(t), "r"(n))
#define TC_RELINQ() \
    asm volatile("tcgen05.relinquish_alloc_permit.cta_group::1.sync.aligned;")
#define TC_COMMIT(m) \
    asm volatile("tcgen05.commit.cta_group::1.mbarrier::arrive::one.shared::cluster.b64 [%0];" \
                 :: "r"(m) : "memory")
#define TC_FENCE_AFTER()  asm volatile("tcgen05.fence::after_thread_sync;" ::: "memory")
#define TC_FENCE_BEFORE() asm volatile("tcgen05.fence::before_thread_sync;" ::: "memory")
#define TC_WAIT_LD()      asm volatile("tcgen05.wait::ld.sync.aligned;" ::: "memory")

__device__ __forceinline__ void mma_bf16_ss(uint32_t d, uint64_t ad, uint64_t bd,
                                            uint32_t idesc, uint32_t en) {
    asm volatile(
        "{\n\t.reg .pred p;\n\t"
        "setp.ne.u32 p, %4, 0;\n\t"
        "tcgen05.mma.cta_group::1.kind::f16 [%0], %1, %2, %3, {%5,%5,%5,%5}, p;\n\t}"
        :: "r"(d), "l"(ad), "l"(bd), "r"(idesc), "r"(en), "r"(0u) : "memory");
}

__device__ __forceinline__ void ldtm32(uint32_t* r, uint32_t taddr) {
    asm volatile(
        "tcgen05.ld.sync.aligned.32x32b.x32.b32 "
        "{%0, %1, %2, %3, %4, %5, %6, %7, %8, %9, %10, %11, %12, %13, %14, %15, "
        "%16, %17, %18, %19, %20, %21, %22, %23, %24, %25, %26, %27, %28, %29, %30, %31}, [%32];"
        : "=r"(r[0]), "=r"(r[1]), "=r"(r[2]), "=r"(r[3]), "=r"(r[4]), "=r"(r[5]),
          "=r"(r[6]), "=r"(r[7]), "=r"(r[8]), "=r"(r[9]), "=r"(r[10]), "=r"(r[11]),
          "=r"(r[12]), "=r"(r[13]), "=r"(r[14]), "=r"(r[15]), "=r"(r[16]), "=r"(r[17]),
          "=r"(r[18]), "=r"(r[19]), "=r"(r[20]), "=r"(r[21]), "=r"(r[22]), "=r"(r[23]),
          "=r"(r[24]), "=r"(r[25]), "=r"(r[26]), "=r"(r[27]), "=r"(r[28]), "=r"(r[29]),
          "=r"(r[30]), "=r"(r[31])
        : "r"(taddr));
}
#endif  // USE_TCGEN05

// Baseline-ISA warp MMA — fallback body
__device__ __forceinline__ void hmma16816(float* d, const uint32_t* a, const uint32_t* b) {
    asm volatile(
        "mma.sync.aligned.m16n8k16.row.col.f32.bf16.bf16.f32 "
        "{%0,%1,%2,%3}, {%4,%5,%6,%7}, {%8,%9}, {%0,%1,%2,%3};"
        : "+f"(d[0]), "+f"(d[1]), "+f"(d[2]), "+f"(d[3])
        : "r"(a[0]), "r"(a[1]), "r"(a[2]), "r"(a[3]), "r"(b[0]), "r"(b[1]));
}

__device__ __forceinline__ void split_bf16(float v, __nv_bfloat16& hi, __nv_bfloat16& lo) {
    hi = __float2bfloat16(v);
    lo = __float2bfloat16(v - __bfloat162float(hi));
}

// ---------------------------------------------------------------------------
// Weight prep: concatenated transposed split weights.
// ---------------------------------------------------------------------------
__global__ void prep_wcat_kernel(const float* __restrict__ Wa,
                                 const float* __restrict__ Wb,
                                 __nv_bfloat16* __restrict__ Thi,
                                 __nv_bfloat16* __restrict__ Tlo,
                                 int Korig, int Kpad)
{
    int idx = blockIdx.x * blockDim.x + threadIdx.x;
    if (idx >= NCAT * Kpad) return;
    int n = idx / Kpad;
    int k = idx - n * Kpad;
    float v = 0.f;
    if (k < Korig)
        v = (n < 1536) ? Wa[(size_t)k * 1536 + n] : Wb[(size_t)k * 512 + (n - 1536)];
    __nv_bfloat16 hi, lo;
    split_bf16(v, hi, lo);
    Thi[idx] = hi;
    Tlo[idx] = lo;
}

// ---------------------------------------------------------------------------
// Embedding gather + split, ALL levels in one launch
// ---------------------------------------------------------------------------
__global__ void gather_x_all_kernel(const float* __restrict__ embed,
                                    const int* __restrict__ vix,     // [L*N]
                                    const float* __restrict__ tmask, // [L*N]
                                    __nv_bfloat16* __restrict__ xhi,
                                    __nv_bfloat16* __restrict__ xlo)
{
    int idx = blockIdx.x * blockDim.x + threadIdx.x;
    const int QE = EPAD / 2;  // 160
    if (idx >= Ll * Nn * QE) return;
    int n = idx / QE;
    int e = (idx - n * QE) * 2;
    float m = tmask[n];
    float v0 = 0.f, v1 = 0.f;
    if (e < Ee) {
        const float* er = embed + (size_t)vix[n] * Ee + e;
        v0 = er[0] * m;
        v1 = er[1] * m;
    }
    __nv_bfloat16 h0, l0, h1, l1;
    split_bf16(v0, h0, l0);
    split_bf16(v1, h1, l1);
    *(__nv_bfloat162*)(xhi + (size_t)n * EPAD + e) = __nv_bfloat162(h0, h1);
    *(__nv_bfloat162*)(xlo + (size_t)n * EPAD + e) = __nv_bfloat162(l0, l1);
}

// ---------------------------------------------------------------------------
// Split-bf16 GEMM: C[M,Ncol] = (Ahi+Alo)[M,Ks] @ (Bhi+Blo)[Ncol,Ks]^T
// Tile: 256 (M) x 256 (N) per CTA, two TMEM accumulator regions, K-chunks of
// 32 (SW64 layout), 3-stage pipeline with hi/lo SUB-STAGE completion:
//   fullA[s] gates (Ahi,Bhi) -> 4 hi*hi MMAs start half-a-stage early
//   fullB[s] gates (Alo,Blo) -> remaining 8 MMAs
//   one commit per chunk recycles the stage (empty[s] / done)
// ---------------------------------------------------------------------------
#define STAGE_BYTES 65536   // Ahi 16K | Alo 16K | Bhi 16K | Blo 16K (256 rows x 64B)
#define NSTAGE 3
#define GEMM_SMEM   (NSTAGE * STAGE_BYTES + 1024)

__global__ void __launch_bounds__(256)
gemm_split_kernel(const __grid_constant__ CUtensorMap tmAhi,
                  const __grid_constant__ CUtensorMap tmAlo,
                  const __grid_constant__ CUtensorMap tmBhi,
                  const __grid_constant__ CUtensorMap tmBlo,
                  const __nv_bfloat16* __restrict__ Ahi,
                  const __nv_bfloat16* __restrict__ Alo,
                  const __nv_bfloat16* __restrict__ Bhi,
                  const __nv_bfloat16* __restrict__ Blo,
                  float* __restrict__ C,
                  int M, int Ks, int Ncol)
{
#if USE_TCGEN05
    extern __shared__ char smem_raw[];
    const uint32_t sb = smem_u32(smem_raw);
    // ctrl: [0] tmem ptr; fullA@16,24,32  empty@40,48,56  done@64  fullB@72,80,88
    const uint32_t ctrl = sb;
    const uint32_t tiles = (sb + 128 + 1023) & ~1023u;

    const int tid = threadIdx.x;
    const int wid = tid >> 5;
    const int lid = tid & 31;
    const int m0 = blockIdx.y * 256;
    const int n0 = blockIdx.x * 256;
    const int NC = Ks >> 5;

    // Leaf-level f-block tiles are never read (leaf node_update uses iou only)
    if (M == Ll * Nn && n0 >= 1536 && m0 >= 5 * Nn) return;

    if (wid == 0) TC_ALLOC(ctrl, 512);
    if (tid == 0) {
        MBAR_INIT(ctrl + 16, 1);    // fullA[0]
        MBAR_INIT(ctrl + 24, 1);    // fullA[1]
        MBAR_INIT(ctrl + 32, 1);    // fullA[2]
        MBAR_INIT(ctrl + 40, 1);    // empty[0]
        MBAR_INIT(ctrl + 48, 1);    // empty[1]
        MBAR_INIT(ctrl + 56, 1);    // empty[2]
        MBAR_INIT(ctrl + 64, 1);    // done
        MBAR_INIT(ctrl + 72, 1);    // fullB[0]
        MBAR_INIT(ctrl + 80, 1);    // fullB[1]
        MBAR_INIT(ctrl + 88, 1);    // fullB[2]
    }
    __syncthreads();
    uint32_t tmem;
    asm("ld.shared.b32 %0, [%1];" : "=r"(tmem) : "r"(ctrl));

    if (wid == 4) {
        // ------------------- producer (1 elected thread) -------------------
        if (elect1()) {
            int s = 0, it = 0;
            for (int c = 0; c < NC; c++) {
                const uint32_t ph = 1u ^ ((uint32_t)it & 1u);
                mbar_wait(ctrl + 40 + s * 8, ph);   // fresh-barrier pass on first visit
                const uint32_t fA = ctrl + 16 + s * 8;
                const uint32_t fB = ctrl + 72 + s * 8;
                const uint32_t tb = tiles + s * STAGE_BYTES;
                const int kx = c * 32;
                MBAR_EXPECT_TX(fA, 32768);
                tma2d(tb,         &tmAhi, kx, m0, fA);
                tma2d(tb + 32768, &tmBhi, kx, n0, fA);
                MBAR_EXPECT_TX(fB, 32768);
                tma2d(tb + 16384, &tmAlo, kx, m0, fB);
                tma2d(tb + 49152, &tmBlo, kx, n0, fB);
                if (++s == NSTAGE) { s = 0; it++; }
            }
        }
    } else if (wid == 0 && elect1()) {
        // ------------------- consumer (1 thread) -------------------
        int s = 0, it = 0;
        for (int c = 0; c < NC; c++) {
            const uint32_t ph = (uint32_t)it & 1u;
            const uint32_t tb = tiles + s * STAGE_BYTES;

            // sub-stage A: hi*hi MMAs as soon as (Ahi,Bhi) land
            mbar_wait(ctrl + 16 + s * 8, ph);
#pragma unroll
            for (int mh = 0; mh < 2; mh++) {
                const uint32_t dtm = tmem + mh * 256;
                uint64_t dah = MAKE_DESC64(tb + mh * 8192);
                uint64_t dbh = MAKE_DESC64(tb + 32768);
#pragma unroll
                for (int ks = 0; ks < 2; ks++)
                    mma_bf16_ss(dtm, dah + 2 * ks, dbh + 2 * ks, IDESC_N256,
                                (c == 0 && ks == 0) ? 0u : 1u);
            }

            // sub-stage B: cross terms once (Alo,Blo) land
            mbar_wait(ctrl + 72 + s * 8, ph);
#pragma unroll
            for (int mh = 0; mh < 2; mh++) {
                const uint32_t dtm = tmem + mh * 256;
                uint64_t dah = MAKE_DESC64(tb + mh * 8192);
                uint64_t dal = MAKE_DESC64(tb + 16384 + mh * 8192);
                uint64_t dbh = MAKE_DESC64(tb + 32768);
                uint64_t dbl = MAKE_DESC64(tb + 49152);
#pragma unroll
                for (int ks = 0; ks < 2; ks++)
                    mma_bf16_ss(dtm, dah + 2 * ks, dbl + 2 * ks, IDESC_N256, 1u);
#pragma unroll
                for (int ks = 0; ks < 2; ks++)
                    mma_bf16_ss(dtm, dal + 2 * ks, dbh + 2 * ks, IDESC_N256, 1u);
            }
            TC_COMMIT((c == NC - 1) ? (ctrl + 64) : (ctrl + 40 + s * 8));
            if (++s == NSTAGE) { s = 0; it++; }
        }
    }

    // ------------------- epilogue (warps 0-3) -------------------
    if (wid < 4) {
        mbar_wait(ctrl + 64, 0);
        TC_FENCE_AFTER();
#pragma unroll
        for (int mh = 0; mh < 2; mh++) {
            float* crow = C + (size_t)(m0 + mh * 128 + wid * 32 + lid) * Ncol + n0;
#pragma unroll
            for (int b = 0; b < 8; b++) {
                uint32_t r[32];
                ldtm32(r, tmem + mh * 256 + b * 32);
                TC_WAIT_LD();
#pragma unroll
                for (int j = 0; j < 32; j += 4) {
                    float4 v;
                    v.x = __uint_as_float(r[j + 0]);
                    v.y = __uint_as_float(r[j + 1]);
                    v.z = __uint_as_float(r[j + 2]);
                    v.w = __uint_as_float(r[j + 3]);
                    *(float4*)(crow + b * 32 + j) = v;
                }
            }
        }
        TC_FENCE_BEFORE();
    }

    __syncthreads();
    if (wid == 0) {
        TC_RELINQ();
        TC_DEALLOC(tmem, 512);
    }

#else  // ------------------------- mma.sync fallback -------------------------
    extern __shared__ char smem_raw[];
    const int tid = threadIdx.x;
    const int wid = tid >> 5;
    const int lane = tid & 31;
    const int wm = wid >> 1;
    const int wn = wid & 1;
    const int r4 = lane >> 2;
    const int tig = lane & 3;
    const int NC = Ks >> 5;

    if (M == Ll * Nn && (blockIdx.x * 256) >= 1536 && (blockIdx.y * 256) >= 5 * Nn)
        return;

    for (int mq = 0; mq < 2; mq++) {
        const int m0 = blockIdx.y * 256 + mq * 128;
        for (int half = 0; half < 2; half++) {
            const int n0 = blockIdx.x * 256 + half * 128;

            float acc[2][8][4];
#pragma unroll
            for (int i = 0; i < 2; i++)
#pragma unroll
                for (int j = 0; j < 8; j++)
#pragma unroll
                    for (int v = 0; v < 4; v++) acc[i][j][v] = 0.f;

            auto ldtile = [&](int buf, int k0) {
                uint32_t tb = smem_u32(smem_raw) + buf * 40960;
#pragma unroll
                for (int q = tid; q < 512; q += 256) {
                    int row = q >> 2;
                    int c = q & 3;
                    uint32_t d = tb + row * 80 + c * 16;
                    size_t ao = (size_t)(m0 + row) * Ks + k0 + c * 8;
                    size_t bo = (size_t)(n0 + row) * Ks + k0 + c * 8;
                    cp16(d,         Ahi + ao);
                    cp16(d + 10240, Alo + ao);
                    cp16(d + 20480, Bhi + bo);
                    cp16(d + 30720, Blo + bo);
                }
                CP_COMMIT();
            };

            ldtile(0, 0);

            for (int c = 0; c < NC; c++) {
                const int cur = c & 1;
                if (c + 1 < NC) {
                    ldtile(cur ^ 1, (c + 1) * 32);
                    CP_WAIT1();
                } else {
                    CP_WAIT0();
                }
                __syncthreads();

                const char* tb = smem_raw + cur * 40960;
#pragma unroll
                for (int kk = 0; kk < 32; kk += 16) {
                    uint32_t ahi[2][4], alo[2][4], bhi[8][2], blo[8][2];
#pragma unroll
                    for (int mi = 0; mi < 2; mi++) {
                        int row = wm * 32 + mi * 16 + r4;
                        int cb = (kk + tig * 2) * 2;
                        ahi[mi][0] = *(const uint32_t*)(tb + row * 80 + cb);
                        ahi[mi][1] = *(const uint32_t*)(tb + (row + 8) * 80 + cb);
                        ahi[mi][2] = *(const uint32_t*)(tb + row * 80 + cb + 16);
                        ahi[mi][3] = *(const uint32_t*)(tb + (row + 8) * 80 + cb + 16);
                        alo[mi][0] = *(const uint32_t*)(tb + 10240 + row * 80 + cb);
                        alo[mi][1] = *(const uint32_t*)(tb + 10240 + (row + 8) * 80 + cb);
                        alo[mi][2] = *(const uint32_t*)(tb + 10240 + row * 80 + cb + 16);
                        alo[mi][3] = *(const uint32_t*)(tb + 10240 + (row + 8) * 80 + cb + 16);
                    }
#pragma unroll
                    for (int ni = 0; ni < 8; ni++) {
                        int nr = wn * 64 + ni * 8 + r4;
                        int cb = (kk + tig * 2) * 2;
                        bhi[ni][0] = *(const uint32_t*)(tb + 20480 + nr * 80 + cb);
                        bhi[ni][1] = *(const uint32_t*)(tb + 20480 + nr * 80 + cb + 16);
                        blo[ni][0] = *(const uint32_t*)(tb + 30720 + nr * 80 + cb);
                        blo[ni][1] = *(const uint32_t*)(tb + 30720 + nr * 80 + cb + 16);
                    }
#pragma unroll
                    for (int mi = 0; mi < 2; mi++)
#pragma unroll
                        for (int ni = 0; ni < 8; ni++) {
                            hmma16816(acc[mi][ni], ahi[mi], bhi[ni]);
                            hmma16816(acc[mi][ni], ahi[mi], blo[ni]);
                            hmma16816(acc[mi][ni], alo[mi], bhi[ni]);
                        }
                }
                __syncthreads();
            }

#pragma unroll
            for (int mi = 0; mi < 2; mi++)
#pragma unroll
                for (int ni = 0; ni < 8; ni++) {
                    int row = m0 + wm * 32 + mi * 16 + r4;
                    int col = n0 + wn * 64 + ni * 8 + tig * 2;
                    *(float2*)(C + (size_t)row * Ncol + col) =
                        make_float2(acc[mi][ni][0], acc[mi][ni][1]);
                    *(float2*)(C + (size_t)(row + 8) * Ncol + col) =
                        make_float2(acc[mi][ni][2], acc[mi][ni][3]);
                }
            __syncthreads();
        }
    }
#endif
}

// ---------------------------------------------------------------------------
// Node update (R10 version: per-child gathers of all hu4 segments)
// ---------------------------------------------------------------------------
__device__ __forceinline__ float sigmoidf_(float v) {
    return 1.f / (1.f + __expf(-v));
}

template <bool LEAF>
__global__ void node_update_kernel(const float* __restrict__ xw4,
                                   const float* __restrict__ hu4,
                                   const float* __restrict__ b_iou,
                                   const float* __restrict__ b_f,
                                   const int* __restrict__ cidx,
                                   const float* __restrict__ cmask,
                                   const float* __restrict__ c_prev,
                                   float* __restrict__ c_out,
                                   __nv_bfloat16* __restrict__ hhi,
                                   __nv_bfloat16* __restrict__ hlo,
                                   float* __restrict__ h_f32)   // may be null
{
    int idx = blockIdx.x * blockDim.x + threadIdx.x;   // over Nn * Hh/2
    if (idx >= Nn * (Hh / 2)) return;
    int n = idx >> 8;              // / 256
    int j = (idx & 255) * 2;

    const float* xw = xw4 + (size_t)n * NCAT;
    float2 gi = *(const float2*)(xw + j);
    float2 go = *(const float2*)(xw + 512 + j);
    float2 gu = *(const float2*)(xw + 1024 + j);
    {
        float2 b0 = *(const float2*)(b_iou + j);
        float2 b1 = *(const float2*)(b_iou + 512 + j);
        float2 b2 = *(const float2*)(b_iou + 1024 + j);
        gi.x += b0.x; gi.y += b0.y;
        go.x += b1.x; go.y += b1.y;
        gu.x += b2.x; gu.y += b2.y;
    }

    float fcx = 0.f, fcy = 0.f;
    if (!LEAF) {
        float2 bf = *(const float2*)(b_f + j);
        float2 xf = *(const float2*)(xw + 1536 + j);
        xf.x += bf.x; xf.y += bf.y;
#pragma unroll
        for (int k = 0; k < Kk; k++) {
            int ci = cidx[n * Kk + k];
            float m = cmask[n * Kk + k];
            const float* hr = hu4 + (size_t)ci * NCAT;
            float2 hi_ = *(const float2*)(hr + j);
            float2 ho_ = *(const float2*)(hr + 512 + j);
            float2 hu_ = *(const float2*)(hr + 1024 + j);
            float2 hf_ = *(const float2*)(hr + 1536 + j);
            gi.x += m * hi_.x; gi.y += m * hi_.y;
            go.x += m * ho_.x; go.y += m * ho_.y;
            gu.x += m * hu_.x; gu.y += m * hu_.y;
            float fx = sigmoidf_(xf.x + m * hf_.x);
            float fy = sigmoidf_(xf.y + m * hf_.y);
            float2 cpv = *(const float2*)(c_prev + (size_t)ci * Hh + j);
            fcx += fx * cpv.x * m;
            fcy += fy * cpv.y * m;
        }
    }

    float cx = sigmoidf_(gi.x) * tanhf(gu.x) + fcx;
    float cy = sigmoidf_(gi.y) * tanhf(gu.y) + fcy;
    *(float2*)(c_out + (size_t)n * Hh + j) = make_float2(cx, cy);

    float hx = sigmoidf_(go.x) * tanhf(cx);
    float hy = sigmoidf_(go.y) * tanhf(cy);

    __nv_bfloat16 h0, l0, h1, l1;
    split_bf16(hx, h0, l0);
    split_bf16(hy, h1, l1);
    *(__nv_bfloat162*)(hhi + (size_t)n * Hh + j) = __nv_bfloat162(h0, h1);
    *(__nv_bfloat162*)(hlo + (size_t)n * Hh + j) = __nv_bfloat162(l0, l1);
    if (h_f32)
        *(float2*)(h_f32 + (size_t)n * Hh + j) = make_float2(hx, hy);
}

// ---------------------------------------------------------------------------
// Host-side tensor map encoding (driver entry point; no -lcuda link needed)
// ---------------------------------------------------------------------------
typedef CUresult (*EncodeTiledFn)(
    CUtensorMap*, CUtensorMapDataType, cuuint32_t, void*,
    const cuuint64_t*, const cuuint64_t*, const cuuint32_t*, const cuuint32_t*,
    CUtensorMapInterleave, CUtensorMapSwizzle, CUtensorMapL2promotion,
    CUtensorMapFloatOOBfill);

static void encode_map(EncodeTiledFn fn, CUtensorMap* m, void* ptr,
                       uint64_t cols, uint64_t rows) {
    cuuint64_t dims[2]    = {cols, rows};
    cuuint64_t strides[1] = {cols * 2};       // bf16 row pitch in bytes
    cuuint32_t box[2]     = {32, 256};        // 64B x 256 rows
    cuuint32_t es[2]      = {1, 1};
    fn(m, CU_TENSOR_MAP_DATA_TYPE_BFLOAT16, 2, ptr, dims, strides, box, es,
       CU_TENSOR_MAP_INTERLEAVE_NONE, CU_TENSOR_MAP_SWIZZLE_64B,
       CU_TENSOR_MAP_L2_PROMOTION_L2_128B, CU_TENSOR_MAP_FLOAT_OOB_FILL_NONE);
}

// ---------------------------------------------------------------------------
// Launch  (R10 schedule)
// ---------------------------------------------------------------------------
extern "C" void kernel_launch(void* const* d_in, const int* in_sizes, int n_in,
                              void* d_out, int out_size)
{
    const int*   vocab_ix   = (const int*)d_in[0];
    const int*   child_idx  = (const int*)d_in[1];
    const float* token_mask = (const float*)d_in[2];
    const float* child_mask = (const float*)d_in[3];
    const float* embed      = (const float*)d_in[4];
    const float* W_iou      = (const float*)d_in[5];   // [E, 3H]
    const float* U_iou      = (const float*)d_in[6];   // [H, 3H]
    const float* b_iou      = (const float*)d_in[7];
    const float* W_f        = (const float*)d_in[8];   // [E, H]
    const float* U_f        = (const float*)d_in[9];   // [H, H]
    const float* b_f        = (const float*)d_in[10];
    float* out = (float*)d_out;

    cudaFuncSetAttribute(gemm_split_kernel,
                         cudaFuncAttributeMaxDynamicSharedMemorySize, GEMM_SMEM);

    __nv_bfloat16 *xhi, *xlo, *hhi, *hlo;
    __nv_bfloat16 *WcatThi, *WcatTlo, *UcatThi, *UcatTlo;
    float *xw4all, *hu4, *cbuf;
    cudaGetSymbolAddress((void**)&xhi, g_xhi);
    cudaGetSymbolAddress((void**)&xlo, g_xlo);
    cudaGetSymbolAddress((void**)&hhi, g_hhi);
    cudaGetSymbolAddress((void**)&hlo, g_hlo);
    cudaGetSymbolAddress((void**)&WcatThi, g_WcatT_hi);
    cudaGetSymbolAddress((void**)&WcatTlo, g_WcatT_lo);
    cudaGetSymbolAddress((void**)&UcatThi, g_UcatT_hi);
    cudaGetSymbolAddress((void**)&UcatTlo, g_UcatT_lo);
    cudaGetSymbolAddress((void**)&xw4all, g_xw4all);
    cudaGetSymbolAddress((void**)&hu4, g_hu4);
    cudaGetSymbolAddress((void**)&cbuf, g_cbuf);

    // Tensor maps (device-global addresses launch-invariant; re-encoded
    // every call -> deterministic, no static guards)
    EncodeTiledFn encode_fn = nullptr;
    {
        void* fp = nullptr;
        cudaDriverEntryPointQueryResult st;
        cudaGetDriverEntryPoint("cuTensorMapEncodeTiled", &fp,
                                cudaEnableDefault, &st);
        encode_fn = (EncodeTiledFn)fp;
    }
    static CUtensorMap tm_xhi, tm_xlo, tm_Whi, tm_Wlo, tm_hhi, tm_hlo, tm_Uhi, tm_Ulo;
    encode_map(encode_fn, &tm_xhi, xhi, EPAD, (uint64_t)Ll * Nn);
    encode_map(encode_fn, &tm_xlo, xlo, EPAD, (uint64_t)Ll * Nn);
    encode_map(encode_fn, &tm_Whi, WcatThi, EPAD, NCAT);
    encode_map(encode_fn, &tm_Wlo, WcatTlo, EPAD, NCAT);
    encode_map(encode_fn, &tm_hhi, hhi, Hh, Nn);
    encode_map(encode_fn, &tm_hlo, hlo, Hh, Nn);
    encode_map(encode_fn, &tm_Uhi, UcatThi, Hh, NCAT);
    encode_map(encode_fn, &tm_Ulo, UcatTlo, Hh, NCAT);

    float* cp[2] = { cbuf, cbuf + (size_t)Nn * Hh };

    const int T = 256;

    // Weight prep + all-level x gather + ALL xw4 GEMMs up front
    prep_wcat_kernel<<<(NCAT * EPAD + T - 1) / T, T>>>(W_iou, W_f, WcatThi, WcatTlo, Ee, EPAD);
    prep_wcat_kernel<<<(NCAT * Hh + T - 1) / T, T>>>(U_iou, U_f, UcatThi, UcatTlo, Hh, Hh);
    gather_x_all_kernel<<<(Ll * Nn * (EPAD / 2) + T - 1) / T, T>>>(
        embed, vocab_ix, token_mask, xhi, xlo);

    // xw4all = x(all levels) @ [W_iou | W_f]   M = 49152, tiles 256x256
    gemm_split_kernel<<<dim3(NCAT / 256, Ll * Nn / 256), 256, GEMM_SMEM>>>(
        tm_xhi, tm_xlo, tm_Whi, tm_Wlo,
        xhi, xlo, WcatThi, WcatTlo, xw4all, Ll * Nn, EPAD, NCAT);

    const int nu_blocks = (Nn * (Hh / 2) + T - 1) / T;

    int cur = 0;
    for (int l = Ll - 1; l >= 0; --l) {
        const bool leaf = (l == Ll - 1);
        const int prev = cur ^ 1;

        if (!leaf) {
            // hu4 = h_prev @ [U_iou | U_f]
            gemm_split_kernel<<<dim3(NCAT / 256, Nn / 256), 256, GEMM_SMEM>>>(
                tm_hhi, tm_hlo, tm_Uhi, tm_Ulo,
                hhi, hlo, UcatThi, UcatTlo, hu4, Nn, Hh, NCAT);
        }

        const float* xw4l = xw4all + (size_t)l * Nn * NCAT;
        float* hf32 = (l == 0) ? out : nullptr;
        if (leaf) {
            node_update_kernel<true><<<nu_blocks, T>>>(
                xw4l, nullptr, b_iou, b_f,
                nullptr, nullptr, nullptr, cp[cur], hhi, hlo, hf32);
        } else {
            node_update_kernel<false><<<nu_blocks, T>>>(
                xw4l, hu4, b_iou, b_f,
                child_idx + l * Nn * Kk, child_mask + l * Nn * Kk,
                cp[prev], cp[cur], hhi, hlo, hf32);
        }
        cur ^= 1;
    }
}

// round 14
// speedup vs baseline: 1.1224x; 1.1133x over previous
#include <cuda_runtime.h>
#include <cuda.h>
#include <cuda_bf16.h>
#include <math.h>
#include <stdint.h>

// Problem constants
#define Vv 50000
#define Ee 300
#define EPAD 320
#define Hh 512
#define Ll 6
#define Nn 8192
#define Kk 4
#define NCAT 2048   // [iou (1536) | f (512)] concatenated output columns

// ---------------------------------------------------------------------------
// Feature gate: tcgen05 exists only on arch-accelerated / family passes.
// ---------------------------------------------------------------------------
#if defined(__CUDA_ARCH__) && (defined(__CUDA_ARCH_FEAT_SM103_ALL) || \
    defined(__CUDA_ARCH_FEAT_SM100_ALL) || defined(__CUDA_ARCH_FEAT_SM110_ALL) || \
    (defined(__CUDA_ARCH_FAMILY_SPECIFIC__) && (__CUDA_ARCH_FAMILY_SPECIFIC__ >= 1000)))
#define USE_TCGEN05 1
#else
#define USE_TCGEN05 0
#endif

// ---------------------------------------------------------------------------
// Scratch
// ---------------------------------------------------------------------------
__device__ __nv_bfloat16 g_xhi[Ll * Nn * EPAD];   // all levels batched
__device__ __nv_bfloat16 g_xlo[Ll * Nn * EPAD];
__device__ __nv_bfloat16 g_hhi[Nn * Hh];
__device__ __nv_bfloat16 g_hlo[Nn * Hh];

__device__ __nv_bfloat16 g_WcatT_hi[NCAT * EPAD];
__device__ __nv_bfloat16 g_WcatT_lo[NCAT * EPAD];
__device__ __nv_bfloat16 g_UcatT_hi[NCAT * Hh];
__device__ __nv_bfloat16 g_UcatT_lo[NCAT * Hh];

__device__ float g_xw4all[(size_t)Ll * Nn * NCAT];  // all-level x @ [W_iou|W_f]
__device__ float g_hu4[Nn * NCAT];                  // h @ [U_iou|U_f]
__device__ float g_cbuf[2 * Nn * Hh];

// ---------------------------------------------------------------------------
// Common PTX helpers
// ---------------------------------------------------------------------------
__device__ __forceinline__ uint32_t smem_u32(const void* p) {
    uint32_t a;
    asm("{ .reg .u64 t; cvta.to.shared.u64 t, %1; cvt.u32.u64 %0, t; }"
        : "=r"(a) : "l"(p));
    return a;
}

__device__ __forceinline__ void cp16(uint32_t dst, const void* src) {
    asm volatile("cp.async.cg.shared.global [%0], [%1], 16;"
                 :: "r"(dst), "l"(src));
}

#define CP_COMMIT()  asm volatile("cp.async.commit_group;" ::: "memory")
#define CP_WAIT0()   asm volatile("cp.async.wait_group 0;" ::: "memory")
#define CP_WAIT1()   asm volatile("cp.async.wait_group 1;" ::: "memory")
#define MBAR_INIT(a, cnt) \
    asm volatile("mbarrier.init.shared.b64 [%0], %1;" :: "r"(a), "r"(cnt) : "memory")
#define MBAR_EXPECT_TX(a, bytes) \
    asm volatile("mbarrier.arrive.expect_tx.shared.b64 _, [%0], %1;" \
                 :: "r"(a), "r"(bytes) : "memory")

// SW64 descriptor (layout 4, SBO=32, LBO=1) — matches TMA SWIZZLE_64B layout
#define DESC_BASE_SW64 ((4ull << 61) | (1ull << 46) | (32ull << 32) | (1ull << 16))
#define MAKE_DESC64(a) (DESC_BASE_SW64 | (((uint64_t)((a) >> 4)) & 0x3FFFull))
// idesc: fp32 accum, bf16 A/B, K-major, M=128, N=256
#define IDESC_N256 (0x10u | 0x80u | 0x400u | (32u << 17) | (8u << 24))

#if USE_TCGEN05
__device__ __forceinline__ uint32_t elect1() {
    uint32_t p;
    asm volatile("{ .reg .pred p; elect.sync _|p, 0xFFFFFFFF; selp.b32 %0,1,0,p; }"
                 : "=r"(p));
    return p;
}

__device__ __forceinline__ void mbar_wait(uint32_t mbar, uint32_t parity) {
    asm volatile(
        "{\n\t.reg .pred P;\n\t"
        "WL_%=:\n\t"
        "mbarrier.try_wait.parity.acquire.cta.shared::cta.b64 P, [%0], %1, 0x989680;\n\t"
        "@P bra.uni WD_%=;\n\t"
        "bra.uni WL_%=;\n\t"
        "WD_%=:\n\t}"
        :: "r"(mbar), "r"(parity) : "memory");
}

__device__ __forceinline__ void tma2d(uint32_t smem, const CUtensorMap* map,
                                      int x, int y, uint32_t mbar) {
    asm volatile(
        "cp.async.bulk.tensor.2d.shared::cta.global.tile.mbarrier::complete_tx::bytes "
        "[%0], [%1, {%2, %3}], [%4];"
        :: "r"(smem), "l"(map), "r"(x), "r"(y), "r"(mbar) : "memory");
}

#define TC_ALLOC(a, n) \
    asm volatile("tcgen05.alloc.cta_group::1.sync.aligned.shared::cta.b32 [%0], %1;" \
                 :: "r"(a), "r"(n) : "memory")
#define TC_DEALLOC(t, n) \
    asm volatile("tcgen05.dealloc.cta_group::1.sync.aligned.b32 %0, %1;" :: "r"(t), "r"(n))
#define TC_RELINQ() \
    asm volatile("tcgen05.relinquish_alloc_permit.cta_group::1.sync.aligned;")
#define TC_COMMIT(m) \
    asm volatile("tcgen05.commit.cta_group::1.mbarrier::arrive::one.shared::cluster.b64 [%0];" \
                 :: "r"(m) : "memory")
#define TC_FENCE_AFTER()  asm volatile("tcgen05.fence::after_thread_sync;" ::: "memory")
#define TC_FENCE_BEFORE() asm volatile("tcgen05.fence::before_thread_sync;" ::: "memory")
#define TC_WAIT_LD()      asm volatile("tcgen05.wait::ld.sync.aligned;" ::: "memory")

__device__ __forceinline__ void mma_bf16_ss(uint32_t d, uint64_t ad, uint64_t bd,
                                            uint32_t idesc, uint32_t en) {
    asm volatile(
        "{\n\t.reg .pred p;\n\t"
        "setp.ne.u32 p, %4, 0;\n\t"
        "tcgen05.mma.cta_group::1.kind::f16 [%0], %1, %2, %3, {%5,%5,%5,%5}, p;\n\t}"
        :: "r"(d), "l"(ad), "l"(bd), "r"(idesc), "r"(en), "r"(0u) : "memory");
}

__device__ __forceinline__ void ldtm32(uint32_t* r, uint32_t taddr) {
    asm volatile(
        "tcgen05.ld.sync.aligned.32x32b.x32.b32 "
        "{%0, %1, %2, %3, %4, %5, %6, %7, %8, %9, %10, %11, %12, %13, %14, %15, "
        "%16, %17, %18, %19, %20, %21, %22, %23, %24, %25, %26, %27, %28, %29, %30, %31}, [%32];"
        : "=r"(r[0]), "=r"(r[1]), "=r"(r[2]), "=r"(r[3]), "=r"(r[4]), "=r"(r[5]),
          "=r"(r[6]), "=r"(r[7]), "=r"(r[8]), "=r"(r[9]), "=r"(r[10]), "=r"(r[11]),
          "=r"(r[12]), "=r"(r[13]), "=r"(r[14]), "=r"(r[15]), "=r"(r[16]), "=r"(r[17]),
          "=r"(r[18]), "=r"(r[19]), "=r"(r[20]), "=r"(r[21]), "=r"(r[22]), "=r"(r[23]),
          "=r"(r[24]), "=r"(r[25]), "=r"(r[26]), "=r"(r[27]), "=r"(r[28]), "=r"(r[29]),
          "=r"(r[30]), "=r"(r[31])
        : "r"(taddr));
}
#endif  // USE_TCGEN05

// Baseline-ISA warp MMA — fallback body
__device__ __forceinline__ void hmma16816(float* d, const uint32_t* a, const uint32_t* b) {
    asm volatile(
        "mma.sync.aligned.m16n8k16.row.col.f32.bf16.bf16.f32 "
        "{%0,%1,%2,%3}, {%4,%5,%6,%7}, {%8,%9}, {%0,%1,%2,%3};"
        : "+f"(d[0]), "+f"(d[1]), "+f"(d[2]), "+f"(d[3])
        : "r"(a[0]), "r"(a[1]), "r"(a[2]), "r"(a[3]), "r"(b[0]), "r"(b[1]));
}

__device__ __forceinline__ void split_bf16(float v, __nv_bfloat16& hi, __nv_bfloat16& lo) {
    hi = __float2bfloat16(v);
    lo = __float2bfloat16(v - __bfloat162float(hi));
}

// ---------------------------------------------------------------------------
// Weight prep: concatenated transposed split weights.
// ---------------------------------------------------------------------------
__global__ void prep_wcat_kernel(const float* __restrict__ Wa,
                                 const float* __restrict__ Wb,
                                 __nv_bfloat16* __restrict__ Thi,
                                 __nv_bfloat16* __restrict__ Tlo,
                                 int Korig, int Kpad)
{
    int idx = blockIdx.x * blockDim.x + threadIdx.x;
    if (idx >= NCAT * Kpad) return;
    int n = idx / Kpad;
    int k = idx - n * Kpad;
    float v = 0.f;
    if (k < Korig)
        v = (n < 1536) ? Wa[(size_t)k * 1536 + n] : Wb[(size_t)k * 512 + (n - 1536)];
    __nv_bfloat16 hi, lo;
    split_bf16(v, hi, lo);
    Thi[idx] = hi;
    Tlo[idx] = lo;
}

// ---------------------------------------------------------------------------
// Embedding gather + split, ALL levels in one launch
// ---------------------------------------------------------------------------
__global__ void gather_x_all_kernel(const float* __restrict__ embed,
                                    const int* __restrict__ vix,     // [L*N]
                                    const float* __restrict__ tmask, // [L*N]
                                    __nv_bfloat16* __restrict__ xhi,
                                    __nv_bfloat16* __restrict__ xlo)
{
    int idx = blockIdx.x * blockDim.x + threadIdx.x;
    const int QE = EPAD / 2;  // 160
    if (idx >= Ll * Nn * QE) return;
    int n = idx / QE;
    int e = (idx - n * QE) * 2;
    float m = tmask[n];
    float v0 = 0.f, v1 = 0.f;
    if (e < Ee) {
        const float* er = embed + (size_t)vix[n] * Ee + e;
        v0 = er[0] * m;
        v1 = er[1] * m;
    }
    __nv_bfloat16 h0, l0, h1, l1;
    split_bf16(v0, h0, l0);
    split_bf16(v1, h1, l1);
    *(__nv_bfloat162*)(xhi + (size_t)n * EPAD + e) = __nv_bfloat162(h0, h1);
    *(__nv_bfloat162*)(xlo + (size_t)n * EPAD + e) = __nv_bfloat162(l0, l1);
}

// ---------------------------------------------------------------------------
// Split-bf16 GEMM (R10 body, verbatim): C = (Ahi+Alo) @ (Bhi+Blo)^T
// Tile: 256x256 per CTA, two TMEM accumulator regions, K-chunks of 32 (SW64),
// 3-stage mbarrier pipeline, TMA bulk loads.
// ---------------------------------------------------------------------------
#define STAGE_BYTES 65536   // Ahi 16K | Alo 16K | Bhi 16K | Blo 16K (256 rows x 64B)
#define NSTAGE 3
#define GEMM_SMEM   (NSTAGE * STAGE_BYTES + 1024)

__global__ void __launch_bounds__(256)
gemm_split_kernel(const __grid_constant__ CUtensorMap tmAhi,
                  const __grid_constant__ CUtensorMap tmAlo,
                  const __grid_constant__ CUtensorMap tmBhi,
                  const __grid_constant__ CUtensorMap tmBlo,
                  const __nv_bfloat16* __restrict__ Ahi,
                  const __nv_bfloat16* __restrict__ Alo,
                  const __nv_bfloat16* __restrict__ Bhi,
                  const __nv_bfloat16* __restrict__ Blo,
                  float* __restrict__ C,
                  int M, int Ks, int Ncol)
{
#if USE_TCGEN05
    extern __shared__ char smem_raw[];
    const uint32_t sb = smem_u32(smem_raw);
    // ctrl: [0] tmem ptr; full@16,24,32  empty@40,48,56  done@64
    const uint32_t ctrl = sb;
    const uint32_t tiles = (sb + 80 + 1023) & ~1023u;

    const int tid = threadIdx.x;
    const int wid = tid >> 5;
    const int lid = tid & 31;
    const int m0 = blockIdx.y * 256;
    const int n0 = blockIdx.x * 256;
    const int NC = Ks >> 5;

    // Leaf-level f-block tiles are never read (leaf node_update uses iou only)
    if (M == Ll * Nn && n0 >= 1536 && m0 >= 5 * Nn) return;

    if (wid == 0) TC_ALLOC(ctrl, 512);
    if (tid == 0) {
        MBAR_INIT(ctrl + 16, 1);    // full[0]  (expect_tx arrive)
        MBAR_INIT(ctrl + 24, 1);    // full[1]
        MBAR_INIT(ctrl + 32, 1);    // full[2]
        MBAR_INIT(ctrl + 40, 1);    // empty[0]
        MBAR_INIT(ctrl + 48, 1);    // empty[1]
        MBAR_INIT(ctrl + 56, 1);    // empty[2]
        MBAR_INIT(ctrl + 64, 1);    // done
    }
    __syncthreads();
    uint32_t tmem;
    asm("ld.shared.b32 %0, [%1];" : "=r"(tmem) : "r"(ctrl));

    if (wid == 4) {
        // ------------------- producer (1 elected thread) -------------------
        if (elect1()) {
            int s = 0, it = 0;
            for (int c = 0; c < NC; c++) {
                const uint32_t ph = 1u ^ ((uint32_t)it & 1u);
                mbar_wait(ctrl + 40 + s * 8, ph);   // fresh-barrier pass on first visit
                const uint32_t fullb = ctrl + 16 + s * 8;
                MBAR_EXPECT_TX(fullb, STAGE_BYTES);
                const uint32_t tb = tiles + s * STAGE_BYTES;
                const int kx = c * 32;
                tma2d(tb,         &tmAhi, kx, m0, fullb);
                tma2d(tb + 16384, &tmAlo, kx, m0, fullb);
                tma2d(tb + 32768, &tmBhi, kx, n0, fullb);
                tma2d(tb + 49152, &tmBlo, kx, n0, fullb);
                if (++s == NSTAGE) { s = 0; it++; }
            }
        }
    } else if (wid == 0 && elect1()) {
        // ------------------- consumer (1 thread) -------------------
        int s = 0, it = 0;
        for (int c = 0; c < NC; c++) {
            const uint32_t ph = (uint32_t)it & 1u;
            mbar_wait(ctrl + 16 + s * 8, ph);
            const uint32_t tb = tiles + s * STAGE_BYTES;
#pragma unroll
            for (int mh = 0; mh < 2; mh++) {
                const uint32_t dtm = tmem + mh * 256;
                uint64_t dah = MAKE_DESC64(tb + mh * 8192);
                uint64_t dal = MAKE_DESC64(tb + 16384 + mh * 8192);
                uint64_t dbh = MAKE_DESC64(tb + 32768);
                uint64_t dbl = MAKE_DESC64(tb + 49152);
#pragma unroll
                for (int ks = 0; ks < 2; ks++)
                    mma_bf16_ss(dtm, dah + 2 * ks, dbh + 2 * ks, IDESC_N256,
                                (c == 0 && ks == 0) ? 0u : 1u);
#pragma unroll
                for (int ks = 0; ks < 2; ks++)
                    mma_bf16_ss(dtm, dah + 2 * ks, dbl + 2 * ks, IDESC_N256, 1u);
#pragma unroll
                for (int ks = 0; ks < 2; ks++)
                    mma_bf16_ss(dtm, dal + 2 * ks, dbh + 2 * ks, IDESC_N256, 1u);
            }
            TC_COMMIT((c == NC - 1) ? (ctrl + 64) : (ctrl + 40 + s * 8));
            if (++s == NSTAGE) { s = 0; it++; }
        }
    }

    // ------------------- epilogue (warps 0-3) -------------------
    if (wid < 4) {
        mbar_wait(ctrl + 64, 0);
        TC_FENCE_AFTER();
#pragma unroll
        for (int mh = 0; mh < 2; mh++) {
            float* crow = C + (size_t)(m0 + mh * 128 + wid * 32 + lid) * Ncol + n0;
#pragma unroll
            for (int b = 0; b < 8; b++) {
                uint32_t r[32];
                ldtm32(r, tmem + mh * 256 + b * 32);
                TC_WAIT_LD();
#pragma unroll
                for (int j = 0; j < 32; j += 4) {
                    float4 v;
                    v.x = __uint_as_float(r[j + 0]);
                    v.y = __uint_as_float(r[j + 1]);
                    v.z = __uint_as_float(r[j + 2]);
                    v.w = __uint_as_float(r[j + 3]);
                    *(float4*)(crow + b * 32 + j) = v;
                }
            }
        }
        TC_FENCE_BEFORE();
    }

    __syncthreads();
    if (wid == 0) {
        TC_RELINQ();
        TC_DEALLOC(tmem, 512);
    }

#else  // ------------------------- mma.sync fallback -------------------------
    extern __shared__ char smem_raw[];
    const int tid = threadIdx.x;
    const int wid = tid >> 5;
    const int lane = tid & 31;
    const int wm = wid >> 1;
    const int wn = wid & 1;
    const int r4 = lane >> 2;
    const int tig = lane & 3;
    const int NC = Ks >> 5;

    if (M == Ll * Nn && (blockIdx.x * 256) >= 1536 && (blockIdx.y * 256) >= 5 * Nn)
        return;

    for (int mq = 0; mq < 2; mq++) {
        const int m0 = blockIdx.y * 256 + mq * 128;
        for (int half = 0; half < 2; half++) {
            const int n0 = blockIdx.x * 256 + half * 128;

            float acc[2][8][4];
#pragma unroll
            for (int i = 0; i < 2; i++)
#pragma unroll
                for (int j = 0; j < 8; j++)
#pragma unroll
                    for (int v = 0; v < 4; v++) acc[i][j][v] = 0.f;

            auto ldtile = [&](int buf, int k0) {
                uint32_t tb = smem_u32(smem_raw) + buf * 40960;
#pragma unroll
                for (int q = tid; q < 512; q += 256) {
                    int row = q >> 2;
                    int c = q & 3;
                    uint32_t d = tb + row * 80 + c * 16;
                    size_t ao = (size_t)(m0 + row) * Ks + k0 + c * 8;
                    size_t bo = (size_t)(n0 + row) * Ks + k0 + c * 8;
                    cp16(d,         Ahi + ao);
                    cp16(d + 10240, Alo + ao);
                    cp16(d + 20480, Bhi + bo);
                    cp16(d + 30720, Blo + bo);
                }
                CP_COMMIT();
            };

            ldtile(0, 0);

            for (int c = 0; c < NC; c++) {
                const int cur = c & 1;
                if (c + 1 < NC) {
                    ldtile(cur ^ 1, (c + 1) * 32);
                    CP_WAIT1();
                } else {
                    CP_WAIT0();
                }
                __syncthreads();

                const char* tb = smem_raw + cur * 40960;
#pragma unroll
                for (int kk = 0; kk < 32; kk += 16) {
                    uint32_t ahi[2][4], alo[2][4], bhi[8][2], blo[8][2];
#pragma unroll
                    for (int mi = 0; mi < 2; mi++) {
                        int row = wm * 32 + mi * 16 + r4;
                        int cb = (kk + tig * 2) * 2;
                        ahi[mi][0] = *(const uint32_t*)(tb + row * 80 + cb);
                        ahi[mi][1] = *(const uint32_t*)(tb + (row + 8) * 80 + cb);
                        ahi[mi][2] = *(const uint32_t*)(tb + row * 80 + cb + 16);
                        ahi[mi][3] = *(const uint32_t*)(tb + (row + 8) * 80 + cb + 16);
                        alo[mi][0] = *(const uint32_t*)(tb + 10240 + row * 80 + cb);
                        alo[mi][1] = *(const uint32_t*)(tb + 10240 + (row + 8) * 80 + cb);
                        alo[mi][2] = *(const uint32_t*)(tb + 10240 + row * 80 + cb + 16);
                        alo[mi][3] = *(const uint32_t*)(tb + 10240 + (row + 8) * 80 + cb + 16);
                    }
#pragma unroll
                    for (int ni = 0; ni < 8; ni++) {
                        int nr = wn * 64 + ni * 8 + r4;
                        int cb = (kk + tig * 2) * 2;
                        bhi[ni][0] = *(const uint32_t*)(tb + 20480 + nr * 80 + cb);
                        bhi[ni][1] = *(const uint32_t*)(tb + 20480 + nr * 80 + cb + 16);
                        blo[ni][0] = *(const uint32_t*)(tb + 30720 + nr * 80 + cb);
                        blo[ni][1] = *(const uint32_t*)(tb + 30720 + nr * 80 + cb + 16);
                    }
#pragma unroll
                    for (int mi = 0; mi < 2; mi++)
#pragma unroll
                        for (int ni = 0; ni < 8; ni++) {
                            hmma16816(acc[mi][ni], ahi[mi], bhi[ni]);
                            hmma16816(acc[mi][ni], ahi[mi], blo[ni]);
                            hmma16816(acc[mi][ni], alo[mi], bhi[ni]);
                        }
                }
                __syncthreads();
            }

#pragma unroll
            for (int mi = 0; mi < 2; mi++)
#pragma unroll
                for (int ni = 0; ni < 8; ni++) {
                    int row = m0 + wm * 32 + mi * 16 + r4;
                    int col = n0 + wn * 64 + ni * 8 + tig * 2;
                    *(float2*)(C + (size_t)row * Ncol + col) =
                        make_float2(acc[mi][ni][0], acc[mi][ni][1]);
                    *(float2*)(C + (size_t)(row + 8) * Ncol + col) =
                        make_float2(acc[mi][ni][2], acc[mi][ni][3]);
                }
            __syncthreads();
        }
    }
#endif
}

// ---------------------------------------------------------------------------
// Node update — float4 per thread (128 threads/node). Same math as R10.
// ---------------------------------------------------------------------------
__device__ __forceinline__ float sigmoidf_(float v) {
    return 1.f / (1.f + __expf(-v));
}

template <bool LEAF>
__global__ void node_update_kernel(const float* __restrict__ xw4,
                                   const float* __restrict__ hu4,
                                   const float* __restrict__ b_iou,
                                   const float* __restrict__ b_f,
                                   const int* __restrict__ cidx,
                                   const float* __restrict__ cmask,
                                   const float* __restrict__ c_prev,
                                   float* __restrict__ c_out,
                                   __nv_bfloat16* __restrict__ hhi,
                                   __nv_bfloat16* __restrict__ hlo,
                                   float* __restrict__ h_f32)   // may be null
{
    int idx = blockIdx.x * blockDim.x + threadIdx.x;   // over Nn * Hh/4
    if (idx >= Nn * (Hh / 4)) return;
    int n = idx >> 7;              // / 128
    int j = (idx & 127) * 4;

    const float* xw = xw4 + (size_t)n * NCAT;
    float4 gi = *(const float4*)(xw + j);
    float4 go = *(const float4*)(xw + 512 + j);
    float4 gu = *(const float4*)(xw + 1024 + j);
    {
        float4 b0 = *(const float4*)(b_iou + j);
        float4 b1 = *(const float4*)(b_iou + 512 + j);
        float4 b2 = *(const float4*)(b_iou + 1024 + j);
        gi.x += b0.x; gi.y += b0.y; gi.z += b0.z; gi.w += b0.w;
        go.x += b1.x; go.y += b1.y; go.z += b1.z; go.w += b1.w;
        gu.x += b2.x; gu.y += b2.y; gu.z += b2.z; gu.w += b2.w;
    }

    float4 fc = make_float4(0.f, 0.f, 0.f, 0.f);
    if (!LEAF) {
        float4 bf = *(const float4*)(b_f + j);
        float4 xf = *(const float4*)(xw + 1536 + j);
        xf.x += bf.x; xf.y += bf.y; xf.z += bf.z; xf.w += bf.w;
#pragma unroll
        for (int k = 0; k < Kk; k++) {
            int ci = cidx[n * Kk + k];
            float m = cmask[n * Kk + k];
            const float* hr = hu4 + (size_t)ci * NCAT;
            float4 hi_ = *(const float4*)(hr + j);
            float4 ho_ = *(const float4*)(hr + 512 + j);
            float4 hu_ = *(const float4*)(hr + 1024 + j);
            float4 hf_ = *(const float4*)(hr + 1536 + j);
            gi.x += m * hi_.x; gi.y += m * hi_.y; gi.z += m * hi_.z; gi.w += m * hi_.w;
            go.x += m * ho_.x; go.y += m * ho_.y; go.z += m * ho_.z; go.w += m * ho_.w;
            gu.x += m * hu_.x; gu.y += m * hu_.y; gu.z += m * hu_.z; gu.w += m * hu_.w;
            float4 cpv = *(const float4*)(c_prev + (size_t)ci * Hh + j);
            fc.x += sigmoidf_(xf.x + m * hf_.x) * cpv.x * m;
            fc.y += sigmoidf_(xf.y + m * hf_.y) * cpv.y * m;
            fc.z += sigmoidf_(xf.z + m * hf_.z) * cpv.z * m;
            fc.w += sigmoidf_(xf.w + m * hf_.w) * cpv.w * m;
        }
    }

    float4 cc;
    cc.x = sigmoidf_(gi.x) * tanhf(gu.x) + fc.x;
    cc.y = sigmoidf_(gi.y) * tanhf(gu.y) + fc.y;
    cc.z = sigmoidf_(gi.z) * tanhf(gu.z) + fc.z;
    cc.w = sigmoidf_(gi.w) * tanhf(gu.w) + fc.w;
    *(float4*)(c_out + (size_t)n * Hh + j) = cc;

    float4 hh;
    hh.x = sigmoidf_(go.x) * tanhf(cc.x);
    hh.y = sigmoidf_(go.y) * tanhf(cc.y);
    hh.z = sigmoidf_(go.z) * tanhf(cc.z);
    hh.w = sigmoidf_(go.w) * tanhf(cc.w);

    __nv_bfloat16 h0, l0, h1, l1, h2, l2, h3, l3;
    split_bf16(hh.x, h0, l0);
    split_bf16(hh.y, h1, l1);
    split_bf16(hh.z, h2, l2);
    split_bf16(hh.w, h3, l3);
    __nv_bfloat162 ph0(h0, h1), ph1(h2, h3), pl0(l0, l1), pl1(l2, l3);
    uint2 uh, ul;
    uh.x = *reinterpret_cast<uint32_t*>(&ph0);
    uh.y = *reinterpret_cast<uint32_t*>(&ph1);
    ul.x = *reinterpret_cast<uint32_t*>(&pl0);
    ul.y = *reinterpret_cast<uint32_t*>(&pl1);
    *(uint2*)(hhi + (size_t)n * Hh + j) = uh;
    *(uint2*)(hlo + (size_t)n * Hh + j) = ul;
    if (h_f32)
        *(float4*)(h_f32 + (size_t)n * Hh + j) = hh;
}

// ---------------------------------------------------------------------------
// Host-side tensor map encoding (driver entry point; no -lcuda link needed)
// ---------------------------------------------------------------------------
typedef CUresult (*EncodeTiledFn)(
    CUtensorMap*, CUtensorMapDataType, cuuint32_t, void*,
    const cuuint64_t*, const cuuint64_t*, const cuuint32_t*, const cuuint32_t*,
    CUtensorMapInterleave, CUtensorMapSwizzle, CUtensorMapL2promotion,
    CUtensorMapFloatOOBfill);

static void encode_map(EncodeTiledFn fn, CUtensorMap* m, void* ptr,
                       uint64_t cols, uint64_t rows) {
    cuuint64_t dims[2]    = {cols, rows};
    cuuint64_t strides[1] = {cols * 2};       // bf16 row pitch in bytes
    cuuint32_t box[2]     = {32, 256};        // 64B x 256 rows
    cuuint32_t es[2]      = {1, 1};
    fn(m, CU_TENSOR_MAP_DATA_TYPE_BFLOAT16, 2, ptr, dims, strides, box, es,
       CU_TENSOR_MAP_INTERLEAVE_NONE, CU_TENSOR_MAP_SWIZZLE_64B,
       CU_TENSOR_MAP_L2_PROMOTION_L2_128B, CU_TENSOR_MAP_FLOAT_OOB_FILL_NONE);
}

// ---------------------------------------------------------------------------
// Launch  (R10 schedule, verbatim)
// ---------------------------------------------------------------------------
extern "C" void kernel_launch(void* const* d_in, const int* in_sizes, int n_in,
                              void* d_out, int out_size)
{
    const int*   vocab_ix   = (const int*)d_in[0];
    const int*   child_idx  = (const int*)d_in[1];
    const float* token_mask = (const float*)d_in[2];
    const float* child_mask = (const float*)d_in[3];
    const float* embed      = (const float*)d_in[4];
    const float* W_iou      = (const float*)d_in[5];   // [E, 3H]
    const float* U_iou      = (const float*)d_in[6];   // [H, 3H]
    const float* b_iou      = (const float*)d_in[7];
    const float* W_f        = (const float*)d_in[8];   // [E, H]
    const float* U_f        = (const float*)d_in[9];   // [H, H]
    const float* b_f        = (const float*)d_in[10];
    float* out = (float*)d_out;

    cudaFuncSetAttribute(gemm_split_kernel,
                         cudaFuncAttributeMaxDynamicSharedMemorySize, GEMM_SMEM);

    __nv_bfloat16 *xhi, *xlo, *hhi, *hlo;
    __nv_bfloat16 *WcatThi, *WcatTlo, *UcatThi, *UcatTlo;
    float *xw4all, *hu4, *cbuf;
    cudaGetSymbolAddress((void**)&xhi, g_xhi);
    cudaGetSymbolAddress((void**)&xlo, g_xlo);
    cudaGetSymbolAddress((void**)&hhi, g_hhi);
    cudaGetSymbolAddress((void**)&hlo, g_hlo);
    cudaGetSymbolAddress((void**)&WcatThi, g_WcatT_hi);
    cudaGetSymbolAddress((void**)&WcatTlo, g_WcatT_lo);
    cudaGetSymbolAddress((void**)&UcatThi, g_UcatT_hi);
    cudaGetSymbolAddress((void**)&UcatTlo, g_UcatT_lo);
    cudaGetSymbolAddress((void**)&xw4all, g_xw4all);
    cudaGetSymbolAddress((void**)&hu4, g_hu4);
    cudaGetSymbolAddress((void**)&cbuf, g_cbuf);

    // Tensor maps (device-global addresses launch-invariant; re-encoded
    // every call -> deterministic, no static guards)
    EncodeTiledFn encode_fn = nullptr;
    {
        void* fp = nullptr;
        cudaDriverEntryPointQueryResult st;
        cudaGetDriverEntryPoint("cuTensorMapEncodeTiled", &fp,
                                cudaEnableDefault, &st);
        encode_fn = (EncodeTiledFn)fp;
    }
    static CUtensorMap tm_xhi, tm_xlo, tm_Whi, tm_Wlo, tm_hhi, tm_hlo, tm_Uhi, tm_Ulo;
    encode_map(encode_fn, &tm_xhi, xhi, EPAD, (uint64_t)Ll * Nn);
    encode_map(encode_fn, &tm_xlo, xlo, EPAD, (uint64_t)Ll * Nn);
    encode_map(encode_fn, &tm_Whi, WcatThi, EPAD, NCAT);
    encode_map(encode_fn, &tm_Wlo, WcatTlo, EPAD, NCAT);
    encode_map(encode_fn, &tm_hhi, hhi, Hh, Nn);
    encode_map(encode_fn, &tm_hlo, hlo, Hh, Nn);
    encode_map(encode_fn, &tm_Uhi, UcatThi, Hh, NCAT);
    encode_map(encode_fn, &tm_Ulo, UcatTlo, Hh, NCAT);

    float* cp[2] = { cbuf, cbuf + (size_t)Nn * Hh };

    const int T = 256;

    // Weight prep + all-level x gather + ALL xw4 GEMMs up front
    prep_wcat_kernel<<<(NCAT * EPAD + T - 1) / T, T>>>(W_iou, W_f, WcatThi, WcatTlo, Ee, EPAD);
    prep_wcat_kernel<<<(NCAT * Hh + T - 1) / T, T>>>(U_iou, U_f, UcatThi, UcatTlo, Hh, Hh);
    gather_x_all_kernel<<<(Ll * Nn * (EPAD / 2) + T - 1) / T, T>>>(
        embed, vocab_ix, token_mask, xhi, xlo);

    // xw4all = x(all levels) @ [W_iou | W_f]   M = 49152, tiles 256x256
    gemm_split_kernel<<<dim3(NCAT / 256, Ll * Nn / 256), 256, GEMM_SMEM>>>(
        tm_xhi, tm_xlo, tm_Whi, tm_Wlo,
        xhi, xlo, WcatThi, WcatTlo, xw4all, Ll * Nn, EPAD, NCAT);

    const int nu_blocks = (Nn * (Hh / 4) + T - 1) / T;

    int cur = 0;
    for (int l = Ll - 1; l >= 0; --l) {
        const bool leaf = (l == Ll - 1);
        const int prev = cur ^ 1;

        if (!leaf) {
            // hu4 = h_prev @ [U_iou | U_f]
            gemm_split_kernel<<<dim3(NCAT / 256, Nn / 256), 256, GEMM_SMEM>>>(
                tm_hhi, tm_hlo, tm_Uhi, tm_Ulo,
                hhi, hlo, UcatThi, UcatTlo, hu4, Nn, Hh, NCAT);
        }

        const float* xw4l = xw4all + (size_t)l * Nn * NCAT;
        float* hf32 = (l == 0) ? out : nullptr;
        if (leaf) {
            node_update_kernel<true><<<nu_blocks, T>>>(
                xw4l, nullptr, b_iou, b_f,
                nullptr, nullptr, nullptr, cp[cur], hhi, hlo, hf32);
        } else {
            node_update_kernel<false><<<nu_blocks, T>>>(
                xw4l, hu4, b_iou, b_f,
                child_idx + l * Nn * Kk, child_mask + l * Nn * Kk,
                cp[prev], cp[cur], hhi, hlo, hf32);
        }
        cur ^= 1;
    }
}

// round 15
// speedup vs baseline: 1.1408x; 1.0164x over previous
#include <cuda_runtime.h>
#include <cuda.h>
#include <cuda_bf16.h>
#include <math.h>
#include <stdint.h>

// Problem constants
#define Vv 50000
#define Ee 300
#define EPAD 320
#define Hh 512
#define Ll 6
#define Nn 8192
#define Kk 4
#define NCAT 2048   // [iou (1536) | f (512)] concatenated output columns

// ---------------------------------------------------------------------------
// Feature gate: tcgen05 exists only on arch-accelerated / family passes.
// ---------------------------------------------------------------------------
#if defined(__CUDA_ARCH__) && (defined(__CUDA_ARCH_FEAT_SM103_ALL) || \
    defined(__CUDA_ARCH_FEAT_SM100_ALL) || defined(__CUDA_ARCH_FEAT_SM110_ALL) || \
    (defined(__CUDA_ARCH_FAMILY_SPECIFIC__) && (__CUDA_ARCH_FAMILY_SPECIFIC__ >= 1000)))
#define USE_TCGEN05 1
#else
#define USE_TCGEN05 0
#endif

// ---------------------------------------------------------------------------
// Scratch
// ---------------------------------------------------------------------------
__device__ __nv_bfloat16 g_xhi[Ll * Nn * EPAD];   // all levels batched
__device__ __nv_bfloat16 g_xlo[Ll * Nn * EPAD];
__device__ __nv_bfloat16 g_hhi[Nn * Hh];
__device__ __nv_bfloat16 g_hlo[Nn * Hh];

__device__ __nv_bfloat16 g_WcatT_hi[NCAT * EPAD];
__device__ __nv_bfloat16 g_WcatT_lo[NCAT * EPAD];
__device__ __nv_bfloat16 g_UcatT_hi[NCAT * Hh];
__device__ __nv_bfloat16 g_UcatT_lo[NCAT * Hh];

__device__ float g_xw4all[(size_t)Ll * Nn * NCAT];  // all-level x @ [W_iou|W_f]
__device__ float g_hu4[Nn * NCAT];                  // h @ [U_iou|U_f]
__device__ float g_cbuf[2 * Nn * Hh];

// ---------------------------------------------------------------------------
// Common PTX helpers
// ---------------------------------------------------------------------------
__device__ __forceinline__ uint32_t smem_u32(const void* p) {
    uint32_t a;
    asm("{ .reg .u64 t; cvta.to.shared.u64 t, %1; cvt.u32.u64 %0, t; }"
        : "=r"(a) : "l"(p));
    return a;
}

__device__ __forceinline__ void cp16(uint32_t dst, const void* src) {
    asm volatile("cp.async.cg.shared.global [%0], [%1], 16;"
                 :: "r"(dst), "l"(src));
}

#define CP_COMMIT()  asm volatile("cp.async.commit_group;" ::: "memory")
#define CP_WAIT0()   asm volatile("cp.async.wait_group 0;" ::: "memory")
#define CP_WAIT1()   asm volatile("cp.async.wait_group 1;" ::: "memory")
#define MBAR_INIT(a, cnt) \
    asm volatile("mbarrier.init.shared.b64 [%0], %1;" :: "r"(a), "r"(cnt) : "memory")
#define MBAR_EXPECT_TX(a, bytes) \
    asm volatile("mbarrier.arrive.expect_tx.shared.b64 _, [%0], %1;" \
                 :: "r"(a), "r"(bytes) : "memory")

// SW64 descriptor (layout 4, SBO=32, LBO=1) — matches TMA SWIZZLE_64B layout
#define DESC_BASE_SW64 ((4ull << 61) | (1ull << 46) | (32ull << 32) | (1ull << 16))
#define MAKE_DESC64(a) (DESC_BASE_SW64 | (((uint64_t)((a) >> 4)) & 0x3FFFull))
// idesc: fp32 accum, bf16 A/B, K-major, M=128, N=256
#define IDESC_N256 (0x10u | 0x80u | 0x400u | (32u << 17) | (8u << 24))

#if USE_TCGEN05
__device__ __forceinline__ uint32_t elect1() {
    uint32_t p;
    asm volatile("{ .reg .pred p; elect.sync _|p, 0xFFFFFFFF; selp.b32 %0,1,0,p; }"
                 : "=r"(p));
    return p;
}

__device__ __forceinline__ void mbar_wait(uint32_t mbar, uint32_t parity) {
    asm volatile(
        "{\n\t.reg .pred P;\n\t"
        "WL_%=:\n\t"
        "mbarrier.try_wait.parity.acquire.cta.shared::cta.b64 P, [%0], %1, 0x989680;\n\t"
        "@P bra.uni WD_%=;\n\t"
        "bra.uni WL_%=;\n\t"
        "WD_%=:\n\t}"
        :: "r"(mbar), "r"(parity) : "memory");
}

__device__ __forceinline__ void tma2d(uint32_t smem, const CUtensorMap* map,
                                      int x, int y, uint32_t mbar) {
    asm volatile(
        "cp.async.bulk.tensor.2d.shared::cta.global.tile.mbarrier::complete_tx::bytes "
        "[%0], [%1, {%2, %3}], [%4];"
        :: "r"(smem), "l"(map), "r"(x), "r"(y), "r"(mbar) : "memory");
}

#define TC_ALLOC(a, n) \
    asm volatile("tcgen05.alloc.cta_group::1.sync.aligned.shared::cta.b32 [%0], %1;" \
                 :: "r"(a), "r"(n) : "memory")
#define TC_DEALLOC(t, n) \
    asm volatile("tcgen05.dealloc.cta_group::1.sync.aligned.b32 %0, %1;" :: "r"(t), "r"(n))
#define TC_RELINQ() \
    asm volatile("tcgen05.relinquish_alloc_permit.cta_group::1.sync.aligned;")
#define TC_COMMIT(m) \
    asm volatile("tcgen05.commit.cta_group::1.mbarrier::arrive::one.shared::cluster.b64 [%0];" \
                 :: "r"(m) : "memory")
#define TC_FENCE_AFTER()  asm volatile("tcgen05.fence::after_thread_sync;" ::: "memory")
#define TC_FENCE_BEFORE() asm volatile("tcgen05.fence::before_thread_sync;" ::: "memory")
#define TC_WAIT_LD()      asm volatile("tcgen05.wait::ld.sync.aligned;" ::: "memory")

__device__ __forceinline__ void mma_bf16_ss(uint32_t d, uint64_t ad, uint64_t bd,
                                            uint32_t idesc, uint32_t en) {
    asm volatile(
        "{\n\t.reg .pred p;\n\t"
        "setp.ne.u32 p, %4, 0;\n\t"
        "tcgen05.mma.cta_group::1.kind::f16 [%0], %1, %2, %3, {%5,%5,%5,%5}, p;\n\t}"
        :: "r"(d), "l"(ad), "l"(bd), "r"(idesc), "r"(en), "r"(0u) : "memory");
}

__device__ __forceinline__ void ldtm32(uint32_t* r, uint32_t taddr) {
    asm volatile(
        "tcgen05.ld.sync.aligned.32x32b.x32.b32 "
        "{%0, %1, %2, %3, %4, %5, %6, %7, %8, %9, %10, %11, %12, %13, %14, %15, "
        "%16, %17, %18, %19, %20, %21, %22, %23, %24, %25, %26, %27, %28, %29, %30, %31}, [%32];"
        : "=r"(r[0]), "=r"(r[1]), "=r"(r[2]), "=r"(r[3]), "=r"(r[4]), "=r"(r[5]),
          "=r"(r[6]), "=r"(r[7]), "=r"(r[8]), "=r"(r[9]), "=r"(r[10]), "=r"(r[11]),
          "=r"(r[12]), "=r"(r[13]), "=r"(r[14]), "=r"(r[15]), "=r"(r[16]), "=r"(r[17]),
          "=r"(r[18]), "=r"(r[19]), "=r"(r[20]), "=r"(r[21]), "=r"(r[22]), "=r"(r[23]),
          "=r"(r[24]), "=r"(r[25]), "=r"(r[26]), "=r"(r[27]), "=r"(r[28]), "=r"(r[29]),
          "=r"(r[30]), "=r"(r[31])
        : "r"(taddr));
}
#endif  // USE_TCGEN05

// Baseline-ISA warp MMA — fallback body
__device__ __forceinline__ void hmma16816(float* d, const uint32_t* a, const uint32_t* b) {
    asm volatile(
        "mma.sync.aligned.m16n8k16.row.col.f32.bf16.bf16.f32 "
        "{%0,%1,%2,%3}, {%4,%5,%6,%7}, {%8,%9}, {%0,%1,%2,%3};"
        : "+f"(d[0]), "+f"(d[1]), "+f"(d[2]), "+f"(d[3])
        : "r"(a[0]), "r"(a[1]), "r"(a[2]), "r"(a[3]), "r"(b[0]), "r"(b[1]));
}

__device__ __forceinline__ void split_bf16(float v, __nv_bfloat16& hi, __nv_bfloat16& lo) {
    hi = __float2bfloat16(v);
    lo = __float2bfloat16(v - __bfloat162float(hi));
}

// ---------------------------------------------------------------------------
// Weight prep: concatenated transposed split weights.
// ---------------------------------------------------------------------------
__global__ void prep_wcat_kernel(const float* __restrict__ Wa,
                                 const float* __restrict__ Wb,
                                 __nv_bfloat16* __restrict__ Thi,
                                 __nv_bfloat16* __restrict__ Tlo,
                                 int Korig, int Kpad)
{
    int idx = blockIdx.x * blockDim.x + threadIdx.x;
    if (idx >= NCAT * Kpad) return;
    int n = idx / Kpad;
    int k = idx - n * Kpad;
    float v = 0.f;
    if (k < Korig)
        v = (n < 1536) ? Wa[(size_t)k * 1536 + n] : Wb[(size_t)k * 512 + (n - 1536)];
    __nv_bfloat16 hi, lo;
    split_bf16(v, hi, lo);
    Thi[idx] = hi;
    Tlo[idx] = lo;
}

// ---------------------------------------------------------------------------
// Embedding gather + split, ALL levels in one launch
// ---------------------------------------------------------------------------
__global__ void gather_x_all_kernel(const float* __restrict__ embed,
                                    const int* __restrict__ vix,     // [L*N]
                                    const float* __restrict__ tmask, // [L*N]
                                    __nv_bfloat16* __restrict__ xhi,
                                    __nv_bfloat16* __restrict__ xlo)
{
    int idx = blockIdx.x * blockDim.x + threadIdx.x;
    const int QE = EPAD / 2;  // 160
    if (idx >= Ll * Nn * QE) return;
    int n = idx / QE;
    int e = (idx - n * QE) * 2;
    float m = tmask[n];
    float v0 = 0.f, v1 = 0.f;
    if (e < Ee) {
        const float* er = embed + (size_t)vix[n] * Ee + e;
        v0 = er[0] * m;
        v1 = er[1] * m;
    }
    __nv_bfloat16 h0, l0, h1, l1;
    split_bf16(v0, h0, l0);
    split_bf16(v1, h1, l1);
    *(__nv_bfloat162*)(xhi + (size_t)n * EPAD + e) = __nv_bfloat162(h0, h1);
    *(__nv_bfloat162*)(xlo + (size_t)n * EPAD + e) = __nv_bfloat162(l0, l1);
}

// ---------------------------------------------------------------------------
// Split-bf16 GEMM (R10/R14 body + uniform A-row offset `arow`):
// C[M,Ncol] = (Ahi+Alo)[arow+M rows, Ks] @ (Bhi+Blo)[Ncol,Ks]^T
// Tile: 256x256 per CTA, two TMEM accumulator regions, K-chunks of 32 (SW64),
// 3-stage mbarrier pipeline, TMA bulk loads.
// ---------------------------------------------------------------------------
#define STAGE_BYTES 65536   // Ahi 16K | Alo 16K | Bhi 16K | Blo 16K (256 rows x 64B)
#define NSTAGE 3
#define GEMM_SMEM   (NSTAGE * STAGE_BYTES + 1024)

__global__ void __launch_bounds__(256)
gemm_split_kernel(const __grid_constant__ CUtensorMap tmAhi,
                  const __grid_constant__ CUtensorMap tmAlo,
                  const __grid_constant__ CUtensorMap tmBhi,
                  const __grid_constant__ CUtensorMap tmBlo,
                  const __nv_bfloat16* __restrict__ Ahi,
                  const __nv_bfloat16* __restrict__ Alo,
                  const __nv_bfloat16* __restrict__ Bhi,
                  const __nv_bfloat16* __restrict__ Blo,
                  float* __restrict__ C,
                  int arow, int Ks, int Ncol)
{
#if USE_TCGEN05
    extern __shared__ char smem_raw[];
    const uint32_t sb = smem_u32(smem_raw);
    // ctrl: [0] tmem ptr; full@16,24,32  empty@40,48,56  done@64
    const uint32_t ctrl = sb;
    const uint32_t tiles = (sb + 80 + 1023) & ~1023u;

    const int tid = threadIdx.x;
    const int wid = tid >> 5;
    const int lid = tid & 31;
    const int m0 = blockIdx.y * 256;
    const int n0 = blockIdx.x * 256;
    const int NC = Ks >> 5;

    if (wid == 0) TC_ALLOC(ctrl, 512);
    if (tid == 0) {
        MBAR_INIT(ctrl + 16, 1);    // full[0]  (expect_tx arrive)
        MBAR_INIT(ctrl + 24, 1);    // full[1]
        MBAR_INIT(ctrl + 32, 1);    // full[2]
        MBAR_INIT(ctrl + 40, 1);    // empty[0]
        MBAR_INIT(ctrl + 48, 1);    // empty[1]
        MBAR_INIT(ctrl + 56, 1);    // empty[2]
        MBAR_INIT(ctrl + 64, 1);    // done
    }
    __syncthreads();
    uint32_t tmem;
    asm("ld.shared.b32 %0, [%1];" : "=r"(tmem) : "r"(ctrl));

    if (wid == 4) {
        // ------------------- producer (1 elected thread) -------------------
        if (elect1()) {
            int s = 0, it = 0;
            for (int c = 0; c < NC; c++) {
                const uint32_t ph = 1u ^ ((uint32_t)it & 1u);
                mbar_wait(ctrl + 40 + s * 8, ph);   // fresh-barrier pass on first visit
                const uint32_t fullb = ctrl + 16 + s * 8;
                MBAR_EXPECT_TX(fullb, STAGE_BYTES);
                const uint32_t tb = tiles + s * STAGE_BYTES;
                const int kx = c * 32;
                tma2d(tb,         &tmAhi, kx, arow + m0, fullb);
                tma2d(tb + 16384, &tmAlo, kx, arow + m0, fullb);
                tma2d(tb + 32768, &tmBhi, kx, n0, fullb);
                tma2d(tb + 49152, &tmBlo, kx, n0, fullb);
                if (++s == NSTAGE) { s = 0; it++; }
            }
        }
    } else if (wid == 0 && elect1()) {
        // ------------------- consumer (1 thread) -------------------
        int s = 0, it = 0;
        for (int c = 0; c < NC; c++) {
            const uint32_t ph = (uint32_t)it & 1u;
            mbar_wait(ctrl + 16 + s * 8, ph);
            const uint32_t tb = tiles + s * STAGE_BYTES;
#pragma unroll
            for (int mh = 0; mh < 2; mh++) {
                const uint32_t dtm = tmem + mh * 256;
                uint64_t dah = MAKE_DESC64(tb + mh * 8192);
                uint64_t dal = MAKE_DESC64(tb + 16384 + mh * 8192);
                uint64_t dbh = MAKE_DESC64(tb + 32768);
                uint64_t dbl = MAKE_DESC64(tb + 49152);
#pragma unroll
                for (int ks = 0; ks < 2; ks++)
                    mma_bf16_ss(dtm, dah + 2 * ks, dbh + 2 * ks, IDESC_N256,
                                (c == 0 && ks == 0) ? 0u : 1u);
#pragma unroll
                for (int ks = 0; ks < 2; ks++)
                    mma_bf16_ss(dtm, dah + 2 * ks, dbl + 2 * ks, IDESC_N256, 1u);
#pragma unroll
                for (int ks = 0; ks < 2; ks++)
                    mma_bf16_ss(dtm, dal + 2 * ks, dbh + 2 * ks, IDESC_N256, 1u);
            }
            TC_COMMIT((c == NC - 1) ? (ctrl + 64) : (ctrl + 40 + s * 8));
            if (++s == NSTAGE) { s = 0; it++; }
        }
    }

    // ------------------- epilogue (warps 0-3) -------------------
    if (wid < 4) {
        mbar_wait(ctrl + 64, 0);
        TC_FENCE_AFTER();
#pragma unroll
        for (int mh = 0; mh < 2; mh++) {
            float* crow = C + (size_t)(m0 + mh * 128 + wid * 32 + lid) * Ncol + n0;
#pragma unroll
            for (int b = 0; b < 8; b++) {
                uint32_t r[32];
                ldtm32(r, tmem + mh * 256 + b * 32);
                TC_WAIT_LD();
#pragma unroll
                for (int j = 0; j < 32; j += 4) {
                    float4 v;
                    v.x = __uint_as_float(r[j + 0]);
                    v.y = __uint_as_float(r[j + 1]);
                    v.z = __uint_as_float(r[j + 2]);
                    v.w = __uint_as_float(r[j + 3]);
                    *(float4*)(crow + b * 32 + j) = v;
                }
            }
        }
        TC_FENCE_BEFORE();
    }

    __syncthreads();
    if (wid == 0) {
        TC_RELINQ();
        TC_DEALLOC(tmem, 512);
    }

#else  // ------------------------- mma.sync fallback -------------------------
    extern __shared__ char smem_raw[];
    const int tid = threadIdx.x;
    const int wid = tid >> 5;
    const int lane = tid & 31;
    const int wm = wid >> 1;
    const int wn = wid & 1;
    const int r4 = lane >> 2;
    const int tig = lane & 3;
    const int NC = Ks >> 5;

    for (int mq = 0; mq < 2; mq++) {
        const int m0 = blockIdx.y * 256 + mq * 128;
        for (int half = 0; half < 2; half++) {
            const int n0 = blockIdx.x * 256 + half * 128;

            float acc[2][8][4];
#pragma unroll
            for (int i = 0; i < 2; i++)
#pragma unroll
                for (int j = 0; j < 8; j++)
#pragma unroll
                    for (int v = 0; v < 4; v++) acc[i][j][v] = 0.f;

            auto ldtile = [&](int buf, int k0) {
                uint32_t tb = smem_u32(smem_raw) + buf * 40960;
#pragma unroll
                for (int q = tid; q < 512; q += 256) {
                    int row = q >> 2;
                    int c = q & 3;
                    uint32_t d = tb + row * 80 + c * 16;
                    size_t ao = (size_t)(arow + m0 + row) * Ks + k0 + c * 8;
                    size_t bo = (size_t)(n0 + row) * Ks + k0 + c * 8;
                    cp16(d,         Ahi + ao);
                    cp16(d + 10240, Alo + ao);
                    cp16(d + 20480, Bhi + bo);
                    cp16(d + 30720, Blo + bo);
                }
                CP_COMMIT();
            };

            ldtile(0, 0);

            for (int c = 0; c < NC; c++) {
                const int cur = c & 1;
                if (c + 1 < NC) {
                    ldtile(cur ^ 1, (c + 1) * 32);
                    CP_WAIT1();
                } else {
                    CP_WAIT0();
                }
                __syncthreads();

                const char* tb = smem_raw + cur * 40960;
#pragma unroll
                for (int kk = 0; kk < 32; kk += 16) {
                    uint32_t ahi[2][4], alo[2][4], bhi[8][2], blo[8][2];
#pragma unroll
                    for (int mi = 0; mi < 2; mi++) {
                        int row = wm * 32 + mi * 16 + r4;
                        int cb = (kk + tig * 2) * 2;
                        ahi[mi][0] = *(const uint32_t*)(tb + row * 80 + cb);
                        ahi[mi][1] = *(const uint32_t*)(tb + (row + 8) * 80 + cb);
                        ahi[mi][2] = *(const uint32_t*)(tb + row * 80 + cb + 16);
                        ahi[mi][3] = *(const uint32_t*)(tb + (row + 8) * 80 + cb + 16);
                        alo[mi][0] = *(const uint32_t*)(tb + 10240 + row * 80 + cb);
                        alo[mi][1] = *(const uint32_t*)(tb + 10240 + (row + 8) * 80 + cb);
                        alo[mi][2] = *(const uint32_t*)(tb + 10240 + row * 80 + cb + 16);
                        alo[mi][3] = *(const uint32_t*)(tb + 10240 + (row + 8) * 80 + cb + 16);
                    }
#pragma unroll
                    for (int ni = 0; ni < 8; ni++) {
                        int nr = wn * 64 + ni * 8 + r4;
                        int cb = (kk + tig * 2) * 2;
                        bhi[ni][0] = *(const uint32_t*)(tb + 20480 + nr * 80 + cb);
                        bhi[ni][1] = *(const uint32_t*)(tb + 20480 + nr * 80 + cb + 16);
                        blo[ni][0] = *(const uint32_t*)(tb + 30720 + nr * 80 + cb);
                        blo[ni][1] = *(const uint32_t*)(tb + 30720 + nr * 80 + cb + 16);
                    }
#pragma unroll
                    for (int mi = 0; mi < 2; mi++)
#pragma unroll
                        for (int ni = 0; ni < 8; ni++) {
                            hmma16816(acc[mi][ni], ahi[mi], bhi[ni]);
                            hmma16816(acc[mi][ni], ahi[mi], blo[ni]);
                            hmma16816(acc[mi][ni], alo[mi], bhi[ni]);
                        }
                }
                __syncthreads();
            }

#pragma unroll
            for (int mi = 0; mi < 2; mi++)
#pragma unroll
                for (int ni = 0; ni < 8; ni++) {
                    int row = m0 + wm * 32 + mi * 16 + r4;
                    int col = n0 + wn * 64 + ni * 8 + tig * 2;
                    *(float2*)(C + (size_t)row * Ncol + col) =
                        make_float2(acc[mi][ni][0], acc[mi][ni][1]);
                    *(float2*)(C + (size_t)(row + 8) * Ncol + col) =
                        make_float2(acc[mi][ni][2], acc[mi][ni][3]);
                }
            __syncthreads();
        }
    }
#endif
}

// ---------------------------------------------------------------------------
// Node update — float4 per thread (128 threads/node).
// ---------------------------------------------------------------------------
__device__ __forceinline__ float sigmoidf_(float v) {
    return 1.f / (1.f + __expf(-v));
}

template <bool LEAF>
__global__ void node_update_kernel(const float* __restrict__ xw4,
                                   const float* __restrict__ hu4,
                                   const float* __restrict__ b_iou,
                                   const float* __restrict__ b_f,
                                   const int* __restrict__ cidx,
                                   const float* __restrict__ cmask,
                                   const float* __restrict__ c_prev,
                                   float* __restrict__ c_out,
                                   __nv_bfloat16* __restrict__ hhi,
                                   __nv_bfloat16* __restrict__ hlo,
                                   float* __restrict__ h_f32)   // may be null
{
    int idx = blockIdx.x * blockDim.x + threadIdx.x;   // over Nn * Hh/4
    if (idx >= Nn * (Hh / 4)) return;
    int n = idx >> 7;              // / 128
    int j = (idx & 127) * 4;

    const float* xw = xw4 + (size_t)n * NCAT;
    float4 gi = *(const float4*)(xw + j);
    float4 go = *(const float4*)(xw + 512 + j);
    float4 gu = *(const float4*)(xw + 1024 + j);
    {
        float4 b0 = *(const float4*)(b_iou + j);
        float4 b1 = *(const float4*)(b_iou + 512 + j);
        float4 b2 = *(const float4*)(b_iou + 1024 + j);
        gi.x += b0.x; gi.y += b0.y; gi.z += b0.z; gi.w += b0.w;
        go.x += b1.x; go.y += b1.y; go.z += b1.z; go.w += b1.w;
        gu.x += b2.x; gu.y += b2.y; gu.z += b2.z; gu.w += b2.w;
    }

    float4 fc = make_float4(0.f, 0.f, 0.f, 0.f);
    if (!LEAF) {
        float4 bf = *(const float4*)(b_f + j);
        float4 xf = *(const float4*)(xw + 1536 + j);
        xf.x += bf.x; xf.y += bf.y; xf.z += bf.z; xf.w += bf.w;
#pragma unroll
        for (int k = 0; k < Kk; k++) {
            int ci = cidx[n * Kk + k];
            float m = cmask[n * Kk + k];
            const float* hr = hu4 + (size_t)ci * NCAT;
            float4 hi_ = *(const float4*)(hr + j);
            float4 ho_ = *(const float4*)(hr + 512 + j);
            float4 hu_ = *(const float4*)(hr + 1024 + j);
            float4 hf_ = *(const float4*)(hr + 1536 + j);
            gi.x += m * hi_.x; gi.y += m * hi_.y; gi.z += m * hi_.z; gi.w += m * hi_.w;
            go.x += m * ho_.x; go.y += m * ho_.y; go.z += m * ho_.z; go.w += m * ho_.w;
            gu.x += m * hu_.x; gu.y += m * hu_.y; gu.z += m * hu_.z; gu.w += m * hu_.w;
            float4 cpv = *(const float4*)(c_prev + (size_t)ci * Hh + j);
            fc.x += sigmoidf_(xf.x + m * hf_.x) * cpv.x * m;
            fc.y += sigmoidf_(xf.y + m * hf_.y) * cpv.y * m;
            fc.z += sigmoidf_(xf.z + m * hf_.z) * cpv.z * m;
            fc.w += sigmoidf_(xf.w + m * hf_.w) * cpv.w * m;
        }
    }

    float4 cc;
    cc.x = sigmoidf_(gi.x) * tanhf(gu.x) + fc.x;
    cc.y = sigmoidf_(gi.y) * tanhf(gu.y) + fc.y;
    cc.z = sigmoidf_(gi.z) * tanhf(gu.z) + fc.z;
    cc.w = sigmoidf_(gi.w) * tanhf(gu.w) + fc.w;
    *(float4*)(c_out + (size_t)n * Hh + j) = cc;

    float4 hh;
    hh.x = sigmoidf_(go.x) * tanhf(cc.x);
    hh.y = sigmoidf_(go.y) * tanhf(cc.y);
    hh.z = sigmoidf_(go.z) * tanhf(cc.z);
    hh.w = sigmoidf_(go.w) * tanhf(cc.w);

    __nv_bfloat16 h0, l0, h1, l1, h2, l2, h3, l3;
    split_bf16(hh.x, h0, l0);
    split_bf16(hh.y, h1, l1);
    split_bf16(hh.z, h2, l2);
    split_bf16(hh.w, h3, l3);
    __nv_bfloat162 ph0(h0, h1), ph1(h2, h3), pl0(l0, l1), pl1(l2, l3);
    uint2 uh, ul;
    uh.x = *reinterpret_cast<uint32_t*>(&ph0);
    uh.y = *reinterpret_cast<uint32_t*>(&ph1);
    ul.x = *reinterpret_cast<uint32_t*>(&pl0);
    ul.y = *reinterpret_cast<uint32_t*>(&pl1);
    *(uint2*)(hhi + (size_t)n * Hh + j) = uh;
    *(uint2*)(hlo + (size_t)n * Hh + j) = ul;
    if (h_f32)
        *(float4*)(h_f32 + (size_t)n * Hh + j) = hh;
}

// ---------------------------------------------------------------------------
// Host-side tensor map encoding (driver entry point; no -lcuda link needed)
// ---------------------------------------------------------------------------
typedef CUresult (*EncodeTiledFn)(
    CUtensorMap*, CUtensorMapDataType, cuuint32_t, void*,
    const cuuint64_t*, const cuuint64_t*, const cuuint32_t*, const cuuint32_t*,
    CUtensorMapInterleave, CUtensorMapSwizzle, CUtensorMapL2promotion,
    CUtensorMapFloatOOBfill);

static void encode_map(EncodeTiledFn fn, CUtensorMap* m, void* ptr,
                       uint64_t cols, uint64_t rows) {
    cuuint64_t dims[2]    = {cols, rows};
    cuuint64_t strides[1] = {cols * 2};       // bf16 row pitch in bytes
    cuuint32_t box[2]     = {32, 256};        // 64B x 256 rows
    cuuint32_t es[2]      = {1, 1};
    fn(m, CU_TENSOR_MAP_DATA_TYPE_BFLOAT16, 2, ptr, dims, strides, box, es,
       CU_TENSOR_MAP_INTERLEAVE_NONE, CU_TENSOR_MAP_SWIZZLE_64B,
       CU_TENSOR_MAP_L2_PROMOTION_L2_128B, CU_TENSOR_MAP_FLOAT_OOB_FILL_NONE);
}

// ---------------------------------------------------------------------------
// Launch — stream-forked schedule:
//   main stream: prep, gather, xw4(leaf), nu(leaf), then per level hu4 -> nu
//   side stream: xw4 per level l=4..0 (independent of recurrence);
//                nu(l) waits evX[l].
// Streams/events created once (host resources; captured graph identical per call).
// ---------------------------------------------------------------------------
extern "C" void kernel_launch(void* const* d_in, const int* in_sizes, int n_in,
                              void* d_out, int out_size)
{
    const int*   vocab_ix   = (const int*)d_in[0];
    const int*   child_idx  = (const int*)d_in[1];
    const float* token_mask = (const float*)d_in[2];
    const float* child_mask = (const float*)d_in[3];
    const float* embed      = (const float*)d_in[4];
    const float* W_iou      = (const float*)d_in[5];   // [E, 3H]
    const float* U_iou      = (const float*)d_in[6];   // [H, 3H]
    const float* b_iou      = (const float*)d_in[7];
    const float* W_f        = (const float*)d_in[8];   // [E, H]
    const float* U_f        = (const float*)d_in[9];   // [H, H]
    const float* b_f        = (const float*)d_in[10];
    float* out = (float*)d_out;

    cudaFuncSetAttribute(gemm_split_kernel,
                         cudaFuncAttributeMaxDynamicSharedMemorySize, GEMM_SMEM);

    __nv_bfloat16 *xhi, *xlo, *hhi, *hlo;
    __nv_bfloat16 *WcatThi, *WcatTlo, *UcatThi, *UcatTlo;
    float *xw4all, *hu4, *cbuf;
    cudaGetSymbolAddress((void**)&xhi, g_xhi);
    cudaGetSymbolAddress((void**)&xlo, g_xlo);
    cudaGetSymbolAddress((void**)&hhi, g_hhi);
    cudaGetSymbolAddress((void**)&hlo, g_hlo);
    cudaGetSymbolAddress((void**)&WcatThi, g_WcatT_hi);
    cudaGetSymbolAddress((void**)&WcatTlo, g_WcatT_lo);
    cudaGetSymbolAddress((void**)&UcatThi, g_UcatT_hi);
    cudaGetSymbolAddress((void**)&UcatTlo, g_UcatT_lo);
    cudaGetSymbolAddress((void**)&xw4all, g_xw4all);
    cudaGetSymbolAddress((void**)&hu4, g_hu4);
    cudaGetSymbolAddress((void**)&cbuf, g_cbuf);

    // Tensor maps (device-global addresses launch-invariant)
    EncodeTiledFn encode_fn = nullptr;
    {
        void* fp = nullptr;
        cudaDriverEntryPointQueryResult st;
        cudaGetDriverEntryPoint("cuTensorMapEncodeTiled", &fp,
                                cudaEnableDefault, &st);
        encode_fn = (EncodeTiledFn)fp;
    }
    static CUtensorMap tm_xhi, tm_xlo, tm_Whi, tm_Wlo, tm_hhi, tm_hlo, tm_Uhi, tm_Ulo;
    encode_map(encode_fn, &tm_xhi, xhi, EPAD, (uint64_t)Ll * Nn);
    encode_map(encode_fn, &tm_xlo, xlo, EPAD, (uint64_t)Ll * Nn);
    encode_map(encode_fn, &tm_Whi, WcatThi, EPAD, NCAT);
    encode_map(encode_fn, &tm_Wlo, WcatTlo, EPAD, NCAT);
    encode_map(encode_fn, &tm_hhi, hhi, Hh, Nn);
    encode_map(encode_fn, &tm_hlo, hlo, Hh, Nn);
    encode_map(encode_fn, &tm_Uhi, UcatThi, Hh, NCAT);
    encode_map(encode_fn, &tm_Ulo, UcatTlo, Hh, NCAT);

    // Side stream + fork/join events (created once; no device memory involved)
    static cudaStream_t s2 = nullptr;
    static cudaEvent_t evFork = nullptr;
    static cudaEvent_t evX[5] = {nullptr, nullptr, nullptr, nullptr, nullptr};
    if (!s2) {
        cudaStreamCreateWithFlags(&s2, cudaStreamNonBlocking);
        cudaEventCreateWithFlags(&evFork, cudaEventDisableTiming);
        for (int i = 0; i < 5; i++)
            cudaEventCreateWithFlags(&evX[i], cudaEventDisableTiming);
    }

    float* cp[2] = { cbuf, cbuf + (size_t)Nn * Hh };

    const int T = 256;

    // Main stream: weight prep + all-level x gather
    prep_wcat_kernel<<<(NCAT * EPAD + T - 1) / T, T>>>(W_iou, W_f, WcatThi, WcatTlo, Ee, EPAD);
    prep_wcat_kernel<<<(NCAT * Hh + T - 1) / T, T>>>(U_iou, U_f, UcatThi, UcatTlo, Hh, Hh);
    gather_x_all_kernel<<<(Ll * Nn * (EPAD / 2) + T - 1) / T, T>>>(
        embed, vocab_ix, token_mask, xhi, xlo);

    // Fork: side stream computes xw4 for levels 4..0 (recurrence-independent)
    cudaEventRecord(evFork, 0);
    cudaStreamWaitEvent(s2, evFork, 0);
    for (int l = 4; l >= 0; --l) {
        gemm_split_kernel<<<dim3(NCAT / 256, Nn / 256), 256, GEMM_SMEM, s2>>>(
            tm_xhi, tm_xlo, tm_Whi, tm_Wlo,
            xhi, xlo, WcatThi, WcatTlo,
            xw4all + (size_t)l * Nn * NCAT, l * Nn, EPAD, NCAT);
        cudaEventRecord(evX[l], s2);
    }

    // Main stream: leaf xw4 (iou columns only) + leaf node update
    gemm_split_kernel<<<dim3(6, Nn / 256), 256, GEMM_SMEM>>>(
        tm_xhi, tm_xlo, tm_Whi, tm_Wlo,
        xhi, xlo, WcatThi, WcatTlo,
        xw4all + (size_t)5 * Nn * NCAT, 5 * Nn, EPAD, NCAT);

    const int nu_blocks = (Nn * (Hh / 4) + T - 1) / T;

    int cur = 0;
    node_update_kernel<true><<<nu_blocks, T>>>(
        xw4all + (size_t)5 * Nn * NCAT, nullptr, b_iou, b_f,
        nullptr, nullptr, nullptr, cp[cur], hhi, hlo, nullptr);
    cur ^= 1;

    for (int l = 4; l >= 0; --l) {
        const int prev = cur ^ 1;

        // hu4 = h_prev @ [U_iou | U_f]
        gemm_split_kernel<<<dim3(NCAT / 256, Nn / 256), 256, GEMM_SMEM>>>(
            tm_hhi, tm_hlo, tm_Uhi, tm_Ulo,
            hhi, hlo, UcatThi, UcatTlo, hu4, 0, Hh, NCAT);

        // join: nu(l) needs xw4 level l from the side stream
        cudaStreamWaitEvent(0, evX[l], 0);

        float* hf32 = (l == 0) ? out : nullptr;
        node_update_kernel<false><<<nu_blocks, T>>>(
            xw4all + (size_t)l * Nn * NCAT, hu4, b_iou, b_f,
            child_idx + l * Nn * Kk, child_mask + l * Nn * Kk,
            cp[prev], cp[cur], hhi, hlo, hf32);
        cur ^= 1;
    }
}